// round 1
// baseline (speedup 1.0000x reference)
#include <cuda_runtime.h>
#include <cstdint>
#include <cstddef>

// Problem constants
#define BB   2
#define NN   2048
#define MM   256
#define CC   1024
#define HH   16
#define HD   64
#define SS   2304   // NN + MM

// Scratch (device globals: no allocation allowed)
__device__ float g_q [(size_t)BB * HH * NN * HD];   // [B,H,N,hd]
__device__ float g_k [(size_t)BB * HH * SS * HD];   // [B,H,S,hd]
__device__ float g_v [(size_t)BB * HH * SS * HD];   // [B,H,S,hd]
__device__ float g_ao[(size_t)BB * NN * CC];        // [B,N,C] attention output

// ---------------------------------------------------------------------------
// Tiled NT GEMM:  out[r,o] = sum_c A[r,c] * W[o,c] + bias[o]
// 128x128 block tile, K-chunk 16, 256 threads, 8x8 micro-tile (split 4+4).
// MODE 0: QKV projection, scatter into g_q/g_k/g_v with per-head layout
// MODE 1: KV projection (text tokens), scatter into g_k/g_v at offset NN
// MODE 2: output projection, A comes from g_ao, plain write to outp
// ---------------------------------------------------------------------------
template <int MODE>
__global__ __launch_bounds__(256) void gemm_nt(const float* __restrict__ A,
                                               const float* __restrict__ W,
                                               const float* __restrict__ bias,
                                               float* __restrict__ outp)
{
    __shared__ float As[16][128];
    __shared__ float Bs[16][128];

    const int tid = threadIdx.x;
    const int tx = tid & 15;
    const int ty = tid >> 4;
    const int rowBase = blockIdx.y * 128;
    const int colBase = blockIdx.x * 128;

    const float* Aptr = (MODE == 2) ? g_ao : A;

    const int m  = tid >> 1;          // 0..127
    const int kq = (tid & 1) * 8;     // 0 or 8
    const float* agp = Aptr + (size_t)(rowBase + m) * CC + kq;
    const float* wgp = W    + (size_t)(colBase + m) * CC + kq;

    float acc[8][8];
#pragma unroll
    for (int i = 0; i < 8; i++)
#pragma unroll
        for (int j = 0; j < 8; j++) acc[i][j] = 0.f;

    for (int k0 = 0; k0 < CC; k0 += 16) {
        float4 a0 = *(const float4*)(agp + k0);
        float4 a1 = *(const float4*)(agp + k0 + 4);
        float4 b0 = *(const float4*)(wgp + k0);
        float4 b1 = *(const float4*)(wgp + k0 + 4);
        __syncthreads();
        As[kq + 0][m] = a0.x; As[kq + 1][m] = a0.y; As[kq + 2][m] = a0.z; As[kq + 3][m] = a0.w;
        As[kq + 4][m] = a1.x; As[kq + 5][m] = a1.y; As[kq + 6][m] = a1.z; As[kq + 7][m] = a1.w;
        Bs[kq + 0][m] = b0.x; Bs[kq + 1][m] = b0.y; Bs[kq + 2][m] = b0.z; Bs[kq + 3][m] = b0.w;
        Bs[kq + 4][m] = b1.x; Bs[kq + 5][m] = b1.y; Bs[kq + 6][m] = b1.z; Bs[kq + 7][m] = b1.w;
        __syncthreads();
#pragma unroll
        for (int kk = 0; kk < 16; kk++) {
            float a[8], b[8];
            *(float4*)&a[0] = *(const float4*)&As[kk][ty * 4];
            *(float4*)&a[4] = *(const float4*)&As[kk][ty * 4 + 64];
            *(float4*)&b[0] = *(const float4*)&Bs[kk][tx * 4];
            *(float4*)&b[4] = *(const float4*)&Bs[kk][tx * 4 + 64];
#pragma unroll
            for (int i = 0; i < 8; i++)
#pragma unroll
                for (int j = 0; j < 8; j++)
                    acc[i][j] += a[i] * b[j];
        }
    }

    // Epilogue: bias + scatter
#pragma unroll
    for (int jj = 0; jj < 2; jj++) {
        const int o0 = colBase + jj * 64 + tx * 4;
        const float4 bv = *(const float4*)&bias[o0];
#pragma unroll
        for (int ii = 0; ii < 2; ii++)
#pragma unroll
            for (int i = 0; i < 4; i++) {
                const int r = rowBase + ii * 64 + ty * 4 + i;
                float4 v;
                v.x = acc[ii * 4 + i][jj * 4 + 0] + bv.x;
                v.y = acc[ii * 4 + i][jj * 4 + 1] + bv.y;
                v.z = acc[ii * 4 + i][jj * 4 + 2] + bv.z;
                v.w = acc[ii * 4 + i][jj * 4 + 3] + bv.w;
                if (MODE == 0) {
                    const int b_ = r >> 11, n = r & (NN - 1);
                    const int three = o0 >> 10, h = (o0 >> 6) & 15, d = o0 & 63;
                    const size_t bh = (size_t)b_ * HH + h;
                    float* dst;
                    if (three == 0)      dst = &g_q[(bh * NN + n) * HD + d];
                    else if (three == 1) dst = &g_k[(bh * SS + n) * HD + d];
                    else                 dst = &g_v[(bh * SS + n) * HD + d];
                    *(float4*)dst = v;
                } else if (MODE == 1) {
                    const int b_ = r >> 8, mm = r & (MM - 1);
                    const int two = o0 >> 10, h = (o0 >> 6) & 15, d = o0 & 63;
                    const size_t bh = (size_t)b_ * HH + h;
                    float* dst = (two == 0) ? &g_k[(bh * SS + NN + mm) * HD + d]
                                            : &g_v[(bh * SS + NN + mm) * HD + d];
                    *(float4*)dst = v;
                } else {
                    *(float4*)&outp[(size_t)r * CC + o0] = v;
                }
            }
    }
}

// ---------------------------------------------------------------------------
// RMSNorm over head_dim=64 rows.  WHICH 0 -> g_q (B*H*N rows), 1 -> g_k (B*H*S)
// One warp per row, 2 elems/thread.
// ---------------------------------------------------------------------------
template <int WHICH>
__global__ __launch_bounds__(256) void rmsnorm_kernel(const float* __restrict__ w)
{
    float* data = (WHICH == 0) ? g_q : g_k;
    const int row  = blockIdx.x * 8 + (threadIdx.x >> 5);
    const int lane = threadIdx.x & 31;
    float* p = data + (size_t)row * HD;
    const float v0 = p[lane];
    const float v1 = p[lane + 32];
    float ss = v0 * v0 + v1 * v1;
#pragma unroll
    for (int o = 16; o; o >>= 1) ss += __shfl_xor_sync(0xffffffffu, ss, o);
    const float inv = rsqrtf(ss * (1.0f / 64.0f) + 1e-6f);
    p[lane]      = v0 * inv * w[lane];
    p[lane + 32] = v1 * inv * w[lane + 32];
}

// ---------------------------------------------------------------------------
// Flash-style attention. Block = 64 queries for one (b,h); loops S in 64-chunks.
// 256 threads (16x16), 4x4 micro-tiles, fp32 online softmax.
// smem: qs[64][68] ks[64][65] vs[64][64] ps[64][65]  (dynamic, 67072 B)
// ---------------------------------------------------------------------------
#define ATTN_SMEM_BYTES (64 * (68 + 65 + 64 + 65) * 4)

__global__ __launch_bounds__(256) void attn_kernel()
{
    extern __shared__ float smem[];
    float* qs = smem;                 // [64][68]
    float* ks = qs + 64 * 68;         // [64][65]
    float* vs = ks + 64 * 65;         // [64][64]
    float* ps = vs + 64 * 64;         // [64][65]

    const int tid = threadIdx.x;
    const int tx = tid & 15;
    const int ty = tid >> 4;
    const int qblk = blockIdx.x;      // 0..31
    const int h = blockIdx.y;         // 0..15
    const int b = blockIdx.z;         // 0..1
    const size_t bh = (size_t)b * HH + h;

    const float* qg = g_q + (bh * NN + (size_t)qblk * 64) * HD;
    const float* kg = g_k + bh * SS * HD;
    const float* vg = g_v + bh * SS * HD;

    // Load Q tile (coalesced float4)
    {
        const int r0 = tid >> 4;             // 0..15
        const int c  = (tid & 15) * 4;       // 0..60
#pragma unroll
        for (int i = 0; i < 4; i++) {
            const int r = r0 + i * 16;
            float4 t = *(const float4*)&qg[r * HD + c];
            *(float4*)&qs[r * 68 + c] = t;
        }
    }

    float acc[4][4];
    float mrow[4], lrow[4];
#pragma unroll
    for (int i = 0; i < 4; i++) {
        mrow[i] = -1e30f;
        lrow[i] = 0.f;
#pragma unroll
        for (int j = 0; j < 4; j++) acc[i][j] = 0.f;
    }
    const float scale = 0.125f;  // 64^-0.5

    for (int sc = 0; sc < SS; sc += 64) {
        __syncthreads();   // prior phase-2 reads of vs/ps done; safe to overwrite ks/vs
        {
            const int r0 = tid >> 4;
            const int c  = (tid & 15) * 4;
#pragma unroll
            for (int i = 0; i < 4; i++) {
                const int r = r0 + i * 16;
                float4 tk = *(const float4*)&kg[(sc + r) * HD + c];
                ks[r * 65 + c + 0] = tk.x; ks[r * 65 + c + 1] = tk.y;
                ks[r * 65 + c + 2] = tk.z; ks[r * 65 + c + 3] = tk.w;
                float4 tv = *(const float4*)&vg[(sc + r) * HD + c];
                *(float4*)&vs[r * 64 + c] = tv;
            }
        }
        __syncthreads();

        // Phase 1: S = Q @ K^T (raw dot products)
        float s[4][4];
#pragma unroll
        for (int i = 0; i < 4; i++)
#pragma unroll
            for (int j = 0; j < 4; j++) s[i][j] = 0.f;
#pragma unroll 8
        for (int d = 0; d < 64; d++) {
            float a[4], bb[4];
#pragma unroll
            for (int i = 0; i < 4; i++) a[i]  = qs[(ty * 4 + i) * 68 + d];
#pragma unroll
            for (int j = 0; j < 4; j++) bb[j] = ks[(tx * 4 + j) * 65 + d];
#pragma unroll
            for (int i = 0; i < 4; i++)
#pragma unroll
                for (int j = 0; j < 4; j++)
                    s[i][j] += a[i] * bb[j];
        }

        // Online softmax
#pragma unroll
        for (int i = 0; i < 4; i++) {
            float mx = s[i][0];
#pragma unroll
            for (int j = 1; j < 4; j++) mx = fmaxf(mx, s[i][j]);
#pragma unroll
            for (int o = 1; o < 16; o <<= 1) mx = fmaxf(mx, __shfl_xor_sync(0xffffffffu, mx, o));
            mx *= scale;
            const float mn = fmaxf(mrow[i], mx);
            const float corr = __expf(mrow[i] - mn);
            mrow[i] = mn;
            float rs = 0.f;
#pragma unroll
            for (int j = 0; j < 4; j++) {
                const float p = __expf(s[i][j] * scale - mn);
                ps[(ty * 4 + i) * 65 + tx * 4 + j] = p;
                rs += p;
            }
#pragma unroll
            for (int o = 1; o < 16; o <<= 1) rs += __shfl_xor_sync(0xffffffffu, rs, o);
            lrow[i] = lrow[i] * corr + rs;
#pragma unroll
            for (int j = 0; j < 4; j++) acc[i][j] *= corr;
        }
        __syncthreads();   // ps fully written before phase 2 reads

        // Phase 2: acc += P @ V
#pragma unroll 8
        for (int sj = 0; sj < 64; sj++) {
            float a[4];
#pragma unroll
            for (int i = 0; i < 4; i++) a[i] = ps[(ty * 4 + i) * 65 + sj];
            const float4 bv = *(const float4*)&vs[sj * 64 + tx * 4];
            const float bb[4] = {bv.x, bv.y, bv.z, bv.w};
#pragma unroll
            for (int i = 0; i < 4; i++)
#pragma unroll
                for (int j = 0; j < 4; j++)
                    acc[i][j] += a[i] * bb[j];
        }
    }

    // Epilogue: normalize and write [B,N,C] layout
#pragma unroll
    for (int i = 0; i < 4; i++) {
        const float inv = 1.0f / lrow[i];
        const int n = qblk * 64 + ty * 4 + i;
        float4 v;
        v.x = acc[i][0] * inv;
        v.y = acc[i][1] * inv;
        v.z = acc[i][2] * inv;
        v.w = acc[i][3] * inv;
        *(float4*)&g_ao[((size_t)b * NN + n) * CC + h * HD + tx * 4] = v;
    }
}

// ---------------------------------------------------------------------------
extern "C" void kernel_launch(void* const* d_in, const int* in_sizes, int n_in,
                              void* d_out, int out_size)
{
    const float* x      = (const float*)d_in[0];
    const float* y      = (const float*)d_in[1];
    const float* qkv_w  = (const float*)d_in[2];
    const float* qkv_b  = (const float*)d_in[3];
    const float* kv_w   = (const float*)d_in[4];
    const float* kv_b   = (const float*)d_in[5];
    const float* qn_w   = (const float*)d_in[6];
    const float* kn_w   = (const float*)d_in[7];
    const float* proj_w = (const float*)d_in[8];
    const float* proj_b = (const float*)d_in[9];
    float* out = (float*)d_out;

    (void)in_sizes; (void)n_in; (void)out_size;

    cudaFuncSetAttribute(attn_kernel, cudaFuncAttributeMaxDynamicSharedMemorySize,
                         ATTN_SMEM_BYTES);

    // QKV projection for image tokens: [4096,1024] x [3072,1024]^T
    gemm_nt<0><<<dim3(3 * CC / 128, BB * NN / 128), 256>>>(x, qkv_w, qkv_b, nullptr);
    // KV projection for text tokens: [512,1024] x [2048,1024]^T
    gemm_nt<1><<<dim3(2 * CC / 128, BB * MM / 128), 256>>>(y, kv_w, kv_b, nullptr);
    // RMSNorm q (B*H*N rows) and k (B*H*S rows)
    rmsnorm_kernel<0><<<(BB * HH * NN) / 8, 256>>>(qn_w);
    rmsnorm_kernel<1><<<(BB * HH * SS) / 8, 256>>>(kn_w);
    // Attention
    attn_kernel<<<dim3(NN / 64, HH, BB), 256, ATTN_SMEM_BYTES>>>();
    // Output projection: [4096,1024] x [1024,1024]^T -> d_out
    gemm_nt<2><<<dim3(CC / 128, BB * NN / 128), 256>>>(nullptr, proj_w, proj_b, out);
}

// round 3
// speedup vs baseline: 1.2378x; 1.2378x over previous
#include <cuda_runtime.h>
#include <cstdint>
#include <cstddef>

// Problem constants
#define BB   2
#define NN   2048
#define MM   256
#define CC   1024
#define HH   16
#define HD   64
#define SS   2304   // NN + MM

// Scratch (device globals: no allocation allowed)
__device__ float g_q [(size_t)BB * HH * NN * HD];   // [B,H,N,hd]
__device__ float g_k [(size_t)BB * HH * SS * HD];   // [B,H,S,hd]
__device__ float g_v [(size_t)BB * HH * SS * HD];   // [B,H,S,hd]
__device__ float g_ao[(size_t)BB * NN * CC];        // [B,N,C] attention output

// ---------------------------------------------------------------------------
// tf32 helpers (baseline PTX, works at compute_103 virtual arch)
// ---------------------------------------------------------------------------
__device__ __forceinline__ float tf32r(float x) {
    uint32_t u;
    asm("cvt.rna.tf32.f32 %0, %1;" : "=r"(u) : "f"(x));
    return __uint_as_float(u);
}

// m16n8k8 tf32 mma. a01 = {a0,a2} (row g, cols t,t+4), a23 = {a1,a3} (row g+8),
// b = {b0,b1} (k rows t,t+4 of col g).
__device__ __forceinline__ void mma_tf32(float* c, float2 a01, float2 a23, float2 b) {
    asm volatile(
        "mma.sync.aligned.m16n8k8.row.col.f32.tf32.tf32.f32 "
        "{%0,%1,%2,%3}, {%4,%5,%6,%7}, {%8,%9}, {%0,%1,%2,%3};"
        : "+f"(c[0]), "+f"(c[1]), "+f"(c[2]), "+f"(c[3])
        : "r"(__float_as_uint(a01.x)), "r"(__float_as_uint(a23.x)),
          "r"(__float_as_uint(a01.y)), "r"(__float_as_uint(a23.y)),
          "r"(__float_as_uint(b.x)),  "r"(__float_as_uint(b.y)));
}

// ---------------------------------------------------------------------------
// Tensor-core tf32 NT GEMM:  out[r,o] = sum_c A[r,c] * W[o,c] + bias[o]
// 128x128 CTA tile, K-chunk 32, double-buffered smem, 8 warps (2x4).
// Smem layout per tile: [128 rows][40 floats] where each k-group of 8 is
// stored pair-permuted: slots = {k0,k4,k1,k5,k2,k6,k3,k7}, so each mma
// fragment pair is one aligned LDS.64 (conflict-free with stride 40).
// MODE 0: QKV proj -> scatter q/k/v per-head
// MODE 1: KV  proj -> scatter k/v (text rows at offset NN)
// MODE 2: out proj <- g_ao, plain write
// ---------------------------------------------------------------------------
#define TILE_F   (128 * 40)                 // floats per 128x32 tile buffer
#define GEMM_SMEM (4 * TILE_F * 4)          // A0,B0,A1,B1 = 81920 bytes

template <int MODE>
__global__ __launch_bounds__(256, 1) void gemm_mma(const float* __restrict__ A,
                                                   const float* __restrict__ W,
                                                   const float* __restrict__ bias,
                                                   float* __restrict__ outp)
{
    extern __shared__ float sm[];
    float* bufA[2] = { sm,              sm + 2 * TILE_F };
    float* bufB[2] = { sm + TILE_F,     sm + 3 * TILE_F };

    const int tid  = threadIdx.x;
    const int lane = tid & 31;
    const int wid  = tid >> 5;
    const int wm   = wid >> 2;          // 0..1  (64-row half)
    const int wn   = wid & 3;           // 0..3  (32-col quarter)
    const int gid  = lane >> 2;         // 0..7
    const int tig  = lane & 3;          // 0..3

    const int rowBase = blockIdx.y * 128;
    const int colBase = blockIdx.x * 128;
    const float* Aptr = (MODE == 2) ? g_ao : A;

    // (row, k-group) pairs handled by this thread for loading: id, id+256
    const int id0 = tid;
    // loader lambda replacement: explicit

    float c[4][4][4];
#pragma unroll
    for (int mt = 0; mt < 4; mt++)
#pragma unroll
        for (int nt = 0; nt < 4; nt++)
#pragma unroll
            for (int q = 0; q < 4; q++) c[mt][nt][q] = 0.f;

    // ---- prologue: load chunk 0 straight to smem buffer 0 ----
#pragma unroll
    for (int i = 0; i < 2; i++) {
        const int id  = id0 + 256 * i;
        const int row = id >> 2;
        const int grp = id & 3;
        float4 v0 = *(const float4*)(Aptr + (size_t)(rowBase + row) * CC + grp * 8);
        float4 v1 = *(const float4*)(Aptr + (size_t)(rowBase + row) * CC + grp * 8 + 4);
        float4 lo, hi;
        lo.x = tf32r(v0.x); lo.y = tf32r(v1.x); lo.z = tf32r(v0.y); lo.w = tf32r(v1.y);
        hi.x = tf32r(v0.z); hi.y = tf32r(v1.z); hi.z = tf32r(v0.w); hi.w = tf32r(v1.w);
        *(float4*)&bufA[0][row * 40 + grp * 8]     = lo;
        *(float4*)&bufA[0][row * 40 + grp * 8 + 4] = hi;
        float4 w0 = *(const float4*)(W + (size_t)(colBase + row) * CC + grp * 8);
        float4 w1 = *(const float4*)(W + (size_t)(colBase + row) * CC + grp * 8 + 4);
        lo.x = tf32r(w0.x); lo.y = tf32r(w1.x); lo.z = tf32r(w0.y); lo.w = tf32r(w1.y);
        hi.x = tf32r(w0.z); hi.y = tf32r(w1.z); hi.z = tf32r(w0.w); hi.w = tf32r(w1.w);
        *(float4*)&bufB[0][row * 40 + grp * 8]     = lo;
        *(float4*)&bufB[0][row * 40 + grp * 8 + 4] = hi;
    }
    __syncthreads();

    // ---- main loop over 32 K-chunks ----
    for (int chunk = 0; chunk < 32; ++chunk) {
        const int s = chunk & 1;
        float4 pa[2][2], pb[2][2];
        if (chunk < 31) {
            const int k0 = (chunk + 1) * 32;
#pragma unroll
            for (int i = 0; i < 2; i++) {
                const int id  = id0 + 256 * i;
                const int row = id >> 2;
                const int grp = id & 3;
                pa[i][0] = *(const float4*)(Aptr + (size_t)(rowBase + row) * CC + k0 + grp * 8);
                pa[i][1] = *(const float4*)(Aptr + (size_t)(rowBase + row) * CC + k0 + grp * 8 + 4);
                pb[i][0] = *(const float4*)(W + (size_t)(colBase + row) * CC + k0 + grp * 8);
                pb[i][1] = *(const float4*)(W + (size_t)(colBase + row) * CC + k0 + grp * 8 + 4);
            }
        }

        // compute on buffer s
        const float* As = bufA[s];
        const float* Bs = bufB[s];
#pragma unroll
        for (int kk = 0; kk < 4; kk++) {
            float2 afr[4][2], bfr[4];
            const int cp = kk * 8 + tig * 2;
#pragma unroll
            for (int mt = 0; mt < 4; mt++) {
                const int r0 = wm * 64 + mt * 16 + gid;
                afr[mt][0] = *(const float2*)&As[r0 * 40 + cp];
                afr[mt][1] = *(const float2*)&As[(r0 + 8) * 40 + cp];
            }
#pragma unroll
            for (int nt = 0; nt < 4; nt++) {
                const int n0 = wn * 32 + nt * 8 + gid;
                bfr[nt] = *(const float2*)&Bs[n0 * 40 + cp];
            }
#pragma unroll
            for (int mt = 0; mt < 4; mt++)
#pragma unroll
                for (int nt = 0; nt < 4; nt++)
                    mma_tf32(c[mt][nt], afr[mt][0], afr[mt][1], bfr[nt]);
        }

        if (chunk < 31) {
            float* dA = bufA[s ^ 1];
            float* dB = bufB[s ^ 1];
#pragma unroll
            for (int i = 0; i < 2; i++) {
                const int id  = id0 + 256 * i;
                const int row = id >> 2;
                const int grp = id & 3;
                float4 lo, hi;
                lo.x = tf32r(pa[i][0].x); lo.y = tf32r(pa[i][1].x);
                lo.z = tf32r(pa[i][0].y); lo.w = tf32r(pa[i][1].y);
                hi.x = tf32r(pa[i][0].z); hi.y = tf32r(pa[i][1].z);
                hi.z = tf32r(pa[i][0].w); hi.w = tf32r(pa[i][1].w);
                *(float4*)&dA[row * 40 + grp * 8]     = lo;
                *(float4*)&dA[row * 40 + grp * 8 + 4] = hi;
                lo.x = tf32r(pb[i][0].x); lo.y = tf32r(pb[i][1].x);
                lo.z = tf32r(pb[i][0].y); lo.w = tf32r(pb[i][1].y);
                hi.x = tf32r(pb[i][0].z); hi.y = tf32r(pb[i][1].z);
                hi.z = tf32r(pb[i][0].w); hi.w = tf32r(pb[i][1].w);
                *(float4*)&dB[row * 40 + grp * 8]     = lo;
                *(float4*)&dB[row * 40 + grp * 8 + 4] = hi;
            }
            __syncthreads();
        }
    }

    // ---- epilogue: bias + scatter (float2 per fragment half) ----
    float2 bias2[4];
#pragma unroll
    for (int nt = 0; nt < 4; nt++) {
        const int col = colBase + wn * 32 + nt * 8 + tig * 2;
        bias2[nt] = *(const float2*)&bias[col];
    }

#pragma unroll
    for (int mt = 0; mt < 4; mt++)
#pragma unroll
        for (int nt = 0; nt < 4; nt++)
#pragma unroll
            for (int half = 0; half < 2; half++) {
                const int row = rowBase + wm * 64 + mt * 16 + gid + half * 8;
                const int col = colBase + wn * 32 + nt * 8 + tig * 2;
                float2 v;
                v.x = c[mt][nt][half * 2 + 0] + bias2[nt].x;
                v.y = c[mt][nt][half * 2 + 1] + bias2[nt].y;
                float* dst;
                if (MODE == 0) {
                    const int b_ = row >> 11, n = row & (NN - 1);
                    const int t3 = col >> 10, h = (col >> 6) & 15, d = col & 63;
                    const size_t bh = (size_t)b_ * HH + h;
                    if (t3 == 0)      dst = g_q + (bh * NN + n) * HD + d;
                    else if (t3 == 1) dst = g_k + (bh * SS + n) * HD + d;
                    else              dst = g_v + (bh * SS + n) * HD + d;
                } else if (MODE == 1) {
                    const int b_ = row >> 8, mm = row & (MM - 1);
                    const int t2 = col >> 10, h = (col >> 6) & 15, d = col & 63;
                    const size_t bh = (size_t)b_ * HH + h;
                    dst = (t2 == 0) ? g_k + (bh * SS + NN + mm) * HD + d
                                    : g_v + (bh * SS + NN + mm) * HD + d;
                } else {
                    dst = outp + (size_t)row * CC + col;
                }
                *(float2*)dst = v;
            }
}

// ---------------------------------------------------------------------------
// RMSNorm over head_dim=64 rows.  WHICH 0 -> g_q (B*H*N rows), 1 -> g_k (B*H*S)
// ---------------------------------------------------------------------------
template <int WHICH>
__global__ __launch_bounds__(256) void rmsnorm_kernel(const float* __restrict__ w)
{
    float* data = (WHICH == 0) ? g_q : g_k;
    const int row  = blockIdx.x * 8 + (threadIdx.x >> 5);
    const int lane = threadIdx.x & 31;
    float* p = data + (size_t)row * HD;
    const float v0 = p[lane];
    const float v1 = p[lane + 32];
    float ss = v0 * v0 + v1 * v1;
#pragma unroll
    for (int o = 16; o; o >>= 1) ss += __shfl_xor_sync(0xffffffffu, ss, o);
    const float inv = rsqrtf(ss * (1.0f / 64.0f) + 1e-6f);
    p[lane]      = v0 * inv * w[lane];
    p[lane + 32] = v1 * inv * w[lane + 32];
}

// ---------------------------------------------------------------------------
// Flash-style attention (fp32) — unchanged from round 1 (next round's target).
// ---------------------------------------------------------------------------
#define ATTN_SMEM_BYTES (64 * (68 + 65 + 64 + 65) * 4)

__global__ __launch_bounds__(256) void attn_kernel()
{
    extern __shared__ float smf[];
    float* qs = smf;                  // [64][68]
    float* ks = qs + 64 * 68;         // [64][65]
    float* vs = ks + 64 * 65;         // [64][64]
    float* ps = vs + 64 * 64;         // [64][65]

    const int tid = threadIdx.x;
    const int tx = tid & 15;
    const int ty = tid >> 4;
    const int qblk = blockIdx.x;
    const int h = blockIdx.y;
    const int b = blockIdx.z;
    const size_t bh = (size_t)b * HH + h;

    const float* qg = g_q + (bh * NN + (size_t)qblk * 64) * HD;
    const float* kg = g_k + bh * SS * HD;
    const float* vg = g_v + bh * SS * HD;

    {
        const int r0 = tid >> 4;
        const int c  = (tid & 15) * 4;
#pragma unroll
        for (int i = 0; i < 4; i++) {
            const int r = r0 + i * 16;
            float4 t = *(const float4*)&qg[r * HD + c];
            *(float4*)&qs[r * 68 + c] = t;
        }
    }

    float acc[4][4];
    float mrow[4], lrow[4];
#pragma unroll
    for (int i = 0; i < 4; i++) {
        mrow[i] = -1e30f;
        lrow[i] = 0.f;
#pragma unroll
        for (int j = 0; j < 4; j++) acc[i][j] = 0.f;
    }
    const float scale = 0.125f;

    for (int sc = 0; sc < SS; sc += 64) {
        __syncthreads();
        {
            const int r0 = tid >> 4;
            const int c  = (tid & 15) * 4;
#pragma unroll
            for (int i = 0; i < 4; i++) {
                const int r = r0 + i * 16;
                float4 tk = *(const float4*)&kg[(sc + r) * HD + c];
                ks[r * 65 + c + 0] = tk.x; ks[r * 65 + c + 1] = tk.y;
                ks[r * 65 + c + 2] = tk.z; ks[r * 65 + c + 3] = tk.w;
                float4 tv = *(const float4*)&vg[(sc + r) * HD + c];
                *(float4*)&vs[r * 64 + c] = tv;
            }
        }
        __syncthreads();

        float s[4][4];
#pragma unroll
        for (int i = 0; i < 4; i++)
#pragma unroll
            for (int j = 0; j < 4; j++) s[i][j] = 0.f;
#pragma unroll 8
        for (int d = 0; d < 64; d++) {
            float a[4], bb[4];
#pragma unroll
            for (int i = 0; i < 4; i++) a[i]  = qs[(ty * 4 + i) * 68 + d];
#pragma unroll
            for (int j = 0; j < 4; j++) bb[j] = ks[(tx * 4 + j) * 65 + d];
#pragma unroll
            for (int i = 0; i < 4; i++)
#pragma unroll
                for (int j = 0; j < 4; j++)
                    s[i][j] += a[i] * bb[j];
        }

#pragma unroll
        for (int i = 0; i < 4; i++) {
            float mx = s[i][0];
#pragma unroll
            for (int j = 1; j < 4; j++) mx = fmaxf(mx, s[i][j]);
#pragma unroll
            for (int o = 1; o < 16; o <<= 1) mx = fmaxf(mx, __shfl_xor_sync(0xffffffffu, mx, o));
            mx *= scale;
            const float mn = fmaxf(mrow[i], mx);
            const float corr = __expf(mrow[i] - mn);
            mrow[i] = mn;
            float rs = 0.f;
#pragma unroll
            for (int j = 0; j < 4; j++) {
                const float p = __expf(s[i][j] * scale - mn);
                ps[(ty * 4 + i) * 65 + tx * 4 + j] = p;
                rs += p;
            }
#pragma unroll
            for (int o = 1; o < 16; o <<= 1) rs += __shfl_xor_sync(0xffffffffu, rs, o);
            lrow[i] = lrow[i] * corr + rs;
#pragma unroll
            for (int j = 0; j < 4; j++) acc[i][j] *= corr;
        }
        __syncthreads();

#pragma unroll 8
        for (int sj = 0; sj < 64; sj++) {
            float a[4];
#pragma unroll
            for (int i = 0; i < 4; i++) a[i] = ps[(ty * 4 + i) * 65 + sj];
            const float4 bv = *(const float4*)&vs[sj * 64 + tx * 4];
            const float bb[4] = {bv.x, bv.y, bv.z, bv.w};
#pragma unroll
            for (int i = 0; i < 4; i++)
#pragma unroll
                for (int j = 0; j < 4; j++)
                    acc[i][j] += a[i] * bb[j];
        }
    }

#pragma unroll
    for (int i = 0; i < 4; i++) {
        const float inv = 1.0f / lrow[i];
        const int n = qblk * 64 + ty * 4 + i;
        float4 v;
        v.x = acc[i][0] * inv;
        v.y = acc[i][1] * inv;
        v.z = acc[i][2] * inv;
        v.w = acc[i][3] * inv;
        *(float4*)&g_ao[((size_t)b * NN + n) * CC + h * HD + tx * 4] = v;
    }
}

// ---------------------------------------------------------------------------
extern "C" void kernel_launch(void* const* d_in, const int* in_sizes, int n_in,
                              void* d_out, int out_size)
{
    const float* x      = (const float*)d_in[0];
    const float* y      = (const float*)d_in[1];
    const float* qkv_w  = (const float*)d_in[2];
    const float* qkv_b  = (const float*)d_in[3];
    const float* kv_w   = (const float*)d_in[4];
    const float* kv_b   = (const float*)d_in[5];
    const float* qn_w   = (const float*)d_in[6];
    const float* kn_w   = (const float*)d_in[7];
    const float* proj_w = (const float*)d_in[8];
    const float* proj_b = (const float*)d_in[9];
    float* out = (float*)d_out;

    (void)in_sizes; (void)n_in; (void)out_size;

    cudaFuncSetAttribute(gemm_mma<0>, cudaFuncAttributeMaxDynamicSharedMemorySize, GEMM_SMEM);
    cudaFuncSetAttribute(gemm_mma<1>, cudaFuncAttributeMaxDynamicSharedMemorySize, GEMM_SMEM);
    cudaFuncSetAttribute(gemm_mma<2>, cudaFuncAttributeMaxDynamicSharedMemorySize, GEMM_SMEM);
    cudaFuncSetAttribute(attn_kernel, cudaFuncAttributeMaxDynamicSharedMemorySize, ATTN_SMEM_BYTES);

    // QKV projection (image): [4096,1024] x [3072,1024]^T
    gemm_mma<0><<<dim3(3 * CC / 128, BB * NN / 128), 256, GEMM_SMEM>>>(x, qkv_w, qkv_b, nullptr);
    // KV projection (text): [512,1024] x [2048,1024]^T
    gemm_mma<1><<<dim3(2 * CC / 128, BB * MM / 128), 256, GEMM_SMEM>>>(y, kv_w, kv_b, nullptr);
    // RMSNorm q and k
    rmsnorm_kernel<0><<<(BB * HH * NN) / 8, 256>>>(qn_w);
    rmsnorm_kernel<1><<<(BB * HH * SS) / 8, 256>>>(kn_w);
    // Attention (fp32)
    attn_kernel<<<dim3(NN / 64, HH, BB), 256, ATTN_SMEM_BYTES>>>();
    // Output projection -> d_out
    gemm_mma<2><<<dim3(CC / 128, BB * NN / 128), 256, GEMM_SMEM>>>(nullptr, proj_w, proj_b, out);
}

// round 4
// speedup vs baseline: 2.2745x; 1.8376x over previous
#include <cuda_runtime.h>
#include <cstdint>
#include <cstddef>

// Problem constants
#define BB   2
#define NN   2048
#define MM   256
#define CC   1024
#define HH   16
#define HD   64
#define SS   2304   // NN + MM

// Scratch (device globals: no allocation allowed)
__device__ float g_q [(size_t)BB * HH * NN * HD];   // [B,H,N,hd]
__device__ float g_k [(size_t)BB * HH * SS * HD];   // [B,H,S,hd]
__device__ float g_v [(size_t)BB * HH * SS * HD];   // [B,H,S,hd]
__device__ float g_ao[(size_t)BB * NN * CC];        // [B,N,C] attention output

// ---------------------------------------------------------------------------
// tf32 helpers (baseline PTX, works at compute_103 virtual arch)
// ---------------------------------------------------------------------------
__device__ __forceinline__ float tf32r(float x) {
    uint32_t u;
    asm("cvt.rna.tf32.f32 %0, %1;" : "=r"(u) : "f"(x));
    return __uint_as_float(u);
}

// m16n8k8 tf32 mma. Register order (a0,a1,a2,a3) = (a01.x, a23.x, a01.y, a23.y):
// a01 = {A[g][k_t], A[g][k_{t+4}]}, a23 = same rows +8. b = {B[k_t][n], B[k_{t+4}][n]}.
__device__ __forceinline__ void mma_tf32(float* c, float2 a01, float2 a23, float2 b) {
    asm volatile(
        "mma.sync.aligned.m16n8k8.row.col.f32.tf32.tf32.f32 "
        "{%0,%1,%2,%3}, {%4,%5,%6,%7}, {%8,%9}, {%0,%1,%2,%3};"
        : "+f"(c[0]), "+f"(c[1]), "+f"(c[2]), "+f"(c[3])
        : "r"(__float_as_uint(a01.x)), "r"(__float_as_uint(a23.x)),
          "r"(__float_as_uint(a01.y)), "r"(__float_as_uint(a23.y)),
          "r"(__float_as_uint(b.x)),  "r"(__float_as_uint(b.y)));
}

// ---------------------------------------------------------------------------
// Tensor-core tf32 NT GEMM (unchanged from round 3, passing at rel_err 3.5e-4)
// ---------------------------------------------------------------------------
#define TILE_F   (128 * 40)
#define GEMM_SMEM (4 * TILE_F * 4)

template <int MODE>
__global__ __launch_bounds__(256, 1) void gemm_mma(const float* __restrict__ A,
                                                   const float* __restrict__ W,
                                                   const float* __restrict__ bias,
                                                   float* __restrict__ outp)
{
    extern __shared__ float sm[];
    float* bufA[2] = { sm,          sm + 2 * TILE_F };
    float* bufB[2] = { sm + TILE_F, sm + 3 * TILE_F };

    const int tid  = threadIdx.x;
    const int lane = tid & 31;
    const int wid  = tid >> 5;
    const int wm   = wid >> 2;
    const int wn   = wid & 3;
    const int gid  = lane >> 2;
    const int tig  = lane & 3;

    const int rowBase = blockIdx.y * 128;
    const int colBase = blockIdx.x * 128;
    const float* Aptr = (MODE == 2) ? g_ao : A;
    const int id0 = tid;

    float c[4][4][4];
#pragma unroll
    for (int mt = 0; mt < 4; mt++)
#pragma unroll
        for (int nt = 0; nt < 4; nt++)
#pragma unroll
            for (int q = 0; q < 4; q++) c[mt][nt][q] = 0.f;

#pragma unroll
    for (int i = 0; i < 2; i++) {
        const int id  = id0 + 256 * i;
        const int row = id >> 2;
        const int grp = id & 3;
        float4 v0 = *(const float4*)(Aptr + (size_t)(rowBase + row) * CC + grp * 8);
        float4 v1 = *(const float4*)(Aptr + (size_t)(rowBase + row) * CC + grp * 8 + 4);
        float4 lo, hi;
        lo.x = tf32r(v0.x); lo.y = tf32r(v1.x); lo.z = tf32r(v0.y); lo.w = tf32r(v1.y);
        hi.x = tf32r(v0.z); hi.y = tf32r(v1.z); hi.z = tf32r(v0.w); hi.w = tf32r(v1.w);
        *(float4*)&bufA[0][row * 40 + grp * 8]     = lo;
        *(float4*)&bufA[0][row * 40 + grp * 8 + 4] = hi;
        float4 w0 = *(const float4*)(W + (size_t)(colBase + row) * CC + grp * 8);
        float4 w1 = *(const float4*)(W + (size_t)(colBase + row) * CC + grp * 8 + 4);
        lo.x = tf32r(w0.x); lo.y = tf32r(w1.x); lo.z = tf32r(w0.y); lo.w = tf32r(w1.y);
        hi.x = tf32r(w0.z); hi.y = tf32r(w1.z); hi.z = tf32r(w0.w); hi.w = tf32r(w1.w);
        *(float4*)&bufB[0][row * 40 + grp * 8]     = lo;
        *(float4*)&bufB[0][row * 40 + grp * 8 + 4] = hi;
    }
    __syncthreads();

    for (int chunk = 0; chunk < 32; ++chunk) {
        const int s = chunk & 1;
        float4 pa[2][2], pb[2][2];
        if (chunk < 31) {
            const int k0 = (chunk + 1) * 32;
#pragma unroll
            for (int i = 0; i < 2; i++) {
                const int id  = id0 + 256 * i;
                const int row = id >> 2;
                const int grp = id & 3;
                pa[i][0] = *(const float4*)(Aptr + (size_t)(rowBase + row) * CC + k0 + grp * 8);
                pa[i][1] = *(const float4*)(Aptr + (size_t)(rowBase + row) * CC + k0 + grp * 8 + 4);
                pb[i][0] = *(const float4*)(W + (size_t)(colBase + row) * CC + k0 + grp * 8);
                pb[i][1] = *(const float4*)(W + (size_t)(colBase + row) * CC + k0 + grp * 8 + 4);
            }
        }

        const float* As = bufA[s];
        const float* Bs = bufB[s];
#pragma unroll
        for (int kk = 0; kk < 4; kk++) {
            float2 afr[4][2], bfr[4];
            const int cp = kk * 8 + tig * 2;
#pragma unroll
            for (int mt = 0; mt < 4; mt++) {
                const int r0 = wm * 64 + mt * 16 + gid;
                afr[mt][0] = *(const float2*)&As[r0 * 40 + cp];
                afr[mt][1] = *(const float2*)&As[(r0 + 8) * 40 + cp];
            }
#pragma unroll
            for (int nt = 0; nt < 4; nt++) {
                const int n0 = wn * 32 + nt * 8 + gid;
                bfr[nt] = *(const float2*)&Bs[n0 * 40 + cp];
            }
#pragma unroll
            for (int mt = 0; mt < 4; mt++)
#pragma unroll
                for (int nt = 0; nt < 4; nt++)
                    mma_tf32(c[mt][nt], afr[mt][0], afr[mt][1], bfr[nt]);
        }

        if (chunk < 31) {
            float* dA = bufA[s ^ 1];
            float* dB = bufB[s ^ 1];
#pragma unroll
            for (int i = 0; i < 2; i++) {
                const int id  = id0 + 256 * i;
                const int row = id >> 2;
                const int grp = id & 3;
                float4 lo, hi;
                lo.x = tf32r(pa[i][0].x); lo.y = tf32r(pa[i][1].x);
                lo.z = tf32r(pa[i][0].y); lo.w = tf32r(pa[i][1].y);
                hi.x = tf32r(pa[i][0].z); hi.y = tf32r(pa[i][1].z);
                hi.z = tf32r(pa[i][0].w); hi.w = tf32r(pa[i][1].w);
                *(float4*)&dA[row * 40 + grp * 8]     = lo;
                *(float4*)&dA[row * 40 + grp * 8 + 4] = hi;
                lo.x = tf32r(pb[i][0].x); lo.y = tf32r(pb[i][1].x);
                lo.z = tf32r(pb[i][0].y); lo.w = tf32r(pb[i][1].y);
                hi.x = tf32r(pb[i][0].z); hi.y = tf32r(pb[i][1].z);
                hi.z = tf32r(pb[i][0].w); hi.w = tf32r(pb[i][1].w);
                *(float4*)&dB[row * 40 + grp * 8]     = lo;
                *(float4*)&dB[row * 40 + grp * 8 + 4] = hi;
            }
            __syncthreads();
        }
    }

    float2 bias2[4];
#pragma unroll
    for (int nt = 0; nt < 4; nt++) {
        const int col = colBase + wn * 32 + nt * 8 + tig * 2;
        bias2[nt] = *(const float2*)&bias[col];
    }

#pragma unroll
    for (int mt = 0; mt < 4; mt++)
#pragma unroll
        for (int nt = 0; nt < 4; nt++)
#pragma unroll
            for (int half = 0; half < 2; half++) {
                const int row = rowBase + wm * 64 + mt * 16 + gid + half * 8;
                const int col = colBase + wn * 32 + nt * 8 + tig * 2;
                float2 v;
                v.x = c[mt][nt][half * 2 + 0] + bias2[nt].x;
                v.y = c[mt][nt][half * 2 + 1] + bias2[nt].y;
                float* dst;
                if (MODE == 0) {
                    const int b_ = row >> 11, n = row & (NN - 1);
                    const int t3 = col >> 10, h = (col >> 6) & 15, d = col & 63;
                    const size_t bh = (size_t)b_ * HH + h;
                    if (t3 == 0)      dst = g_q + (bh * NN + n) * HD + d;
                    else if (t3 == 1) dst = g_k + (bh * SS + n) * HD + d;
                    else              dst = g_v + (bh * SS + n) * HD + d;
                } else if (MODE == 1) {
                    const int b_ = row >> 8, mm = row & (MM - 1);
                    const int t2 = col >> 10, h = (col >> 6) & 15, d = col & 63;
                    const size_t bh = (size_t)b_ * HH + h;
                    dst = (t2 == 0) ? g_k + (bh * SS + NN + mm) * HD + d
                                    : g_v + (bh * SS + NN + mm) * HD + d;
                } else {
                    dst = outp + (size_t)row * CC + col;
                }
                *(float2*)dst = v;
            }
}

// ---------------------------------------------------------------------------
// RMSNorm over head_dim=64 rows.
// ---------------------------------------------------------------------------
template <int WHICH>
__global__ __launch_bounds__(256) void rmsnorm_kernel(const float* __restrict__ w)
{
    float* data = (WHICH == 0) ? g_q : g_k;
    const int row  = blockIdx.x * 8 + (threadIdx.x >> 5);
    const int lane = threadIdx.x & 31;
    float* p = data + (size_t)row * HD;
    const float v0 = p[lane];
    const float v1 = p[lane + 32];
    float ss = v0 * v0 + v1 * v1;
#pragma unroll
    for (int o = 16; o; o >>= 1) ss += __shfl_xor_sync(0xffffffffu, ss, o);
    const float inv = rsqrtf(ss * (1.0f / 64.0f) + 1e-6f);
    p[lane]      = v0 * inv * w[lane];
    p[lane + 32] = v1 * inv * w[lane + 32];
}

// ---------------------------------------------------------------------------
// Tensor-core flash attention.
// CTA: 128 queries x one (b,h). 8 warps x 16 query rows. S-chunks of 64.
// smem: qs [128][72] pair-permuted tf32 (A-layout)
//       ks [ 64][72] pair-permuted tf32 (B-layout)
//       vs [ 64][72] plain tf32 (B-frag scalar loads conflict-free)
//       ps [128][72] plain (per-warp private P tiles)
// Pair permutation within each k-group of 8: slots {k0,k4,k1,k5,k2,k6,k3,k7}.
// ---------------------------------------------------------------------------
#define ASTR 72
#define ATTN_SMEM ((128 * ASTR + 64 * ASTR + 64 * ASTR + 128 * ASTR) * 4)

__global__ __launch_bounds__(256, 1) void attn_mma()
{
    extern __shared__ float sm[];
    float* qs = sm;                         // [128][72]
    float* ks = qs + 128 * ASTR;            // [64][72]
    float* vs = ks + 64 * ASTR;             // [64][72]
    float* ps = vs + 64 * ASTR;             // [128][72]

    const int tid  = threadIdx.x;
    const int lane = tid & 31;
    const int wid  = tid >> 5;
    const int gid  = lane >> 2;             // 0..7
    const int tig  = lane & 3;              // 0..3

    const int qb = blockIdx.x * 128;
    const int h  = blockIdx.y;
    const int b  = blockIdx.z;
    const size_t bh = (size_t)b * HH + h;

    const float* qg = g_q + (bh * NN + qb) * HD;
    const float* kg = g_k + bh * SS * HD;
    const float* vg = g_v + bh * SS * HD;

    // ---- load Q tile (pair-permuted, tf32) ----
#pragma unroll
    for (int i = 0; i < 4; i++) {
        const int u = tid + 256 * i;
        const int row = u >> 3, grp = u & 7;
        float4 v0 = *(const float4*)(qg + (size_t)row * HD + grp * 8);
        float4 v1 = *(const float4*)(qg + (size_t)row * HD + grp * 8 + 4);
        float4 lo, hi;
        lo.x = tf32r(v0.x); lo.y = tf32r(v1.x); lo.z = tf32r(v0.y); lo.w = tf32r(v1.y);
        hi.x = tf32r(v0.z); hi.y = tf32r(v1.z); hi.z = tf32r(v0.w); hi.w = tf32r(v1.w);
        *(float4*)&qs[row * ASTR + grp * 8]     = lo;
        *(float4*)&qs[row * ASTR + grp * 8 + 4] = hi;
    }

    // ---- prologue: chunk 0 K/V -> regs -> smem ----
    float4 pk[2][2], pv[4];
#pragma unroll
    for (int i = 0; i < 2; i++) {
        const int u = tid + 256 * i;
        const int row = u >> 3, grp = u & 7;
        pk[i][0] = *(const float4*)(kg + (size_t)row * HD + grp * 8);
        pk[i][1] = *(const float4*)(kg + (size_t)row * HD + grp * 8 + 4);
    }
#pragma unroll
    for (int i = 0; i < 4; i++) {
        const int u = tid + 256 * i;
        const int row = u >> 4, c4 = (u & 15) * 4;
        pv[i] = *(const float4*)(vg + (size_t)row * HD + c4);
    }
#pragma unroll
    for (int i = 0; i < 2; i++) {
        const int u = tid + 256 * i;
        const int row = u >> 3, grp = u & 7;
        float4 lo, hi;
        lo.x = tf32r(pk[i][0].x); lo.y = tf32r(pk[i][1].x);
        lo.z = tf32r(pk[i][0].y); lo.w = tf32r(pk[i][1].y);
        hi.x = tf32r(pk[i][0].z); hi.y = tf32r(pk[i][1].z);
        hi.z = tf32r(pk[i][0].w); hi.w = tf32r(pk[i][1].w);
        *(float4*)&ks[row * ASTR + grp * 8]     = lo;
        *(float4*)&ks[row * ASTR + grp * 8 + 4] = hi;
    }
#pragma unroll
    for (int i = 0; i < 4; i++) {
        const int u = tid + 256 * i;
        const int row = u >> 4, c4 = (u & 15) * 4;
        float4 t = pv[i];
        t.x = tf32r(t.x); t.y = tf32r(t.y); t.z = tf32r(t.z); t.w = tf32r(t.w);
        *(float4*)&vs[row * ASTR + c4] = t;
    }
    __syncthreads();

    // ---- persistent state ----
    float oacc[8][4];
#pragma unroll
    for (int nt = 0; nt < 8; nt++)
#pragma unroll
        for (int q = 0; q < 4; q++) oacc[nt][q] = 0.f;
    float m0 = -1e30f, m1 = -1e30f, l0 = 0.f, l1 = 0.f;
    const float scale = 0.125f;

    const int wrow = wid * 16;
    const float* qw = qs + wrow * ASTR;
    float* pw = ps + wrow * ASTR;
    const int pr0 = gid, pr1 = gid + 8;

    for (int c = 0; c < 36; ++c) {
        // prefetch next chunk
        if (c < 35) {
            const int sc = (c + 1) * 64;
#pragma unroll
            for (int i = 0; i < 2; i++) {
                const int u = tid + 256 * i;
                const int row = u >> 3, grp = u & 7;
                pk[i][0] = *(const float4*)(kg + (size_t)(sc + row) * HD + grp * 8);
                pk[i][1] = *(const float4*)(kg + (size_t)(sc + row) * HD + grp * 8 + 4);
            }
#pragma unroll
            for (int i = 0; i < 4; i++) {
                const int u = tid + 256 * i;
                const int row = u >> 4, c4 = (u & 15) * 4;
                pv[i] = *(const float4*)(vg + (size_t)(sc + row) * HD + c4);
            }
        }

        // ---- phase 1: S = Q @ K^T ----
        float s[8][4];
#pragma unroll
        for (int nt = 0; nt < 8; nt++)
#pragma unroll
            for (int q = 0; q < 4; q++) s[nt][q] = 0.f;
#pragma unroll
        for (int kk = 0; kk < 8; kk++) {
            const int cp = kk * 8 + tig * 2;
            float2 a0 = *(const float2*)&qw[gid * ASTR + cp];
            float2 a1 = *(const float2*)&qw[(gid + 8) * ASTR + cp];
#pragma unroll
            for (int nt = 0; nt < 8; nt++) {
                float2 bq = *(const float2*)&ks[(nt * 8 + gid) * ASTR + cp];
                mma_tf32(s[nt], a0, a1, bq);
            }
        }

        // ---- online softmax ----
        float mx0 = -1e30f, mx1 = -1e30f;
#pragma unroll
        for (int nt = 0; nt < 8; nt++) {
            mx0 = fmaxf(mx0, fmaxf(s[nt][0], s[nt][1]));
            mx1 = fmaxf(mx1, fmaxf(s[nt][2], s[nt][3]));
        }
        mx0 = fmaxf(mx0, __shfl_xor_sync(0xffffffffu, mx0, 1));
        mx0 = fmaxf(mx0, __shfl_xor_sync(0xffffffffu, mx0, 2));
        mx1 = fmaxf(mx1, __shfl_xor_sync(0xffffffffu, mx1, 1));
        mx1 = fmaxf(mx1, __shfl_xor_sync(0xffffffffu, mx1, 2));

        const float mn0 = fmaxf(m0, mx0 * scale);
        const float mn1 = fmaxf(m1, mx1 * scale);
        const float cr0 = __expf(m0 - mn0);
        const float cr1 = __expf(m1 - mn1);
        m0 = mn0; m1 = mn1;

        float rs0 = 0.f, rs1 = 0.f;
#pragma unroll
        for (int nt = 0; nt < 8; nt++) {
            const float p00 = __expf(s[nt][0] * scale - mn0);
            const float p01 = __expf(s[nt][1] * scale - mn0);
            const float p10 = __expf(s[nt][2] * scale - mn1);
            const float p11 = __expf(s[nt][3] * scale - mn1);
            rs0 += p00 + p01;
            rs1 += p10 + p11;
            float2 w0; w0.x = tf32r(p00); w0.y = tf32r(p01);
            float2 w1; w1.x = tf32r(p10); w1.y = tf32r(p11);
            *(float2*)&pw[pr0 * ASTR + nt * 8 + tig * 2] = w0;
            *(float2*)&pw[pr1 * ASTR + nt * 8 + tig * 2] = w1;
        }
        rs0 += __shfl_xor_sync(0xffffffffu, rs0, 1);
        rs0 += __shfl_xor_sync(0xffffffffu, rs0, 2);
        rs1 += __shfl_xor_sync(0xffffffffu, rs1, 1);
        rs1 += __shfl_xor_sync(0xffffffffu, rs1, 2);
        l0 = l0 * cr0 + rs0;
        l1 = l1 * cr1 + rs1;
#pragma unroll
        for (int nt = 0; nt < 8; nt++) {
            oacc[nt][0] *= cr0; oacc[nt][1] *= cr0;
            oacc[nt][2] *= cr1; oacc[nt][3] *= cr1;
        }
        __syncwarp();

        // ---- phase 2: O += P @ V ----
#pragma unroll
        for (int kk = 0; kk < 8; kk++) {
            float2 a0, a1;
            a0.x = pw[pr0 * ASTR + kk * 8 + tig];
            a0.y = pw[pr0 * ASTR + kk * 8 + tig + 4];
            a1.x = pw[pr1 * ASTR + kk * 8 + tig];
            a1.y = pw[pr1 * ASTR + kk * 8 + tig + 4];
#pragma unroll
            for (int nt = 0; nt < 8; nt++) {
                float2 bv;
                bv.x = vs[(kk * 8 + tig) * ASTR + nt * 8 + gid];
                bv.y = vs[(kk * 8 + tig + 4) * ASTR + nt * 8 + gid];
                mma_tf32(oacc[nt], a0, a1, bv);
            }
        }

        __syncthreads();   // all warps done reading ks/vs
        if (c < 35) {
#pragma unroll
            for (int i = 0; i < 2; i++) {
                const int u = tid + 256 * i;
                const int row = u >> 3, grp = u & 7;
                float4 lo, hi;
                lo.x = tf32r(pk[i][0].x); lo.y = tf32r(pk[i][1].x);
                lo.z = tf32r(pk[i][0].y); lo.w = tf32r(pk[i][1].y);
                hi.x = tf32r(pk[i][0].z); hi.y = tf32r(pk[i][1].z);
                hi.z = tf32r(pk[i][0].w); hi.w = tf32r(pk[i][1].w);
                *(float4*)&ks[row * ASTR + grp * 8]     = lo;
                *(float4*)&ks[row * ASTR + grp * 8 + 4] = hi;
            }
#pragma unroll
            for (int i = 0; i < 4; i++) {
                const int u = tid + 256 * i;
                const int row = u >> 4, c4 = (u & 15) * 4;
                float4 t = pv[i];
                t.x = tf32r(t.x); t.y = tf32r(t.y); t.z = tf32r(t.z); t.w = tf32r(t.w);
                *(float4*)&vs[row * ASTR + c4] = t;
            }
            __syncthreads();
        }
    }

    // ---- epilogue: normalize, write [B,N,C] ----
    const float inv0 = 1.0f / l0;
    const float inv1 = 1.0f / l1;
    const int n0 = qb + wrow + gid;
    const int n1 = n0 + 8;
#pragma unroll
    for (int nt = 0; nt < 8; nt++) {
        const int d = h * HD + nt * 8 + tig * 2;
        float2 v0; v0.x = oacc[nt][0] * inv0; v0.y = oacc[nt][1] * inv0;
        float2 v1; v1.x = oacc[nt][2] * inv1; v1.y = oacc[nt][3] * inv1;
        *(float2*)&g_ao[((size_t)b * NN + n0) * CC + d] = v0;
        *(float2*)&g_ao[((size_t)b * NN + n1) * CC + d] = v1;
    }
}

// ---------------------------------------------------------------------------
extern "C" void kernel_launch(void* const* d_in, const int* in_sizes, int n_in,
                              void* d_out, int out_size)
{
    const float* x      = (const float*)d_in[0];
    const float* y      = (const float*)d_in[1];
    const float* qkv_w  = (const float*)d_in[2];
    const float* qkv_b  = (const float*)d_in[3];
    const float* kv_w   = (const float*)d_in[4];
    const float* kv_b   = (const float*)d_in[5];
    const float* qn_w   = (const float*)d_in[6];
    const float* kn_w   = (const float*)d_in[7];
    const float* proj_w = (const float*)d_in[8];
    const float* proj_b = (const float*)d_in[9];
    float* out = (float*)d_out;

    (void)in_sizes; (void)n_in; (void)out_size;

    cudaFuncSetAttribute(gemm_mma<0>, cudaFuncAttributeMaxDynamicSharedMemorySize, GEMM_SMEM);
    cudaFuncSetAttribute(gemm_mma<1>, cudaFuncAttributeMaxDynamicSharedMemorySize, GEMM_SMEM);
    cudaFuncSetAttribute(gemm_mma<2>, cudaFuncAttributeMaxDynamicSharedMemorySize, GEMM_SMEM);
    cudaFuncSetAttribute(attn_mma, cudaFuncAttributeMaxDynamicSharedMemorySize, ATTN_SMEM);

    // QKV projection (image): [4096,1024] x [3072,1024]^T
    gemm_mma<0><<<dim3(3 * CC / 128, BB * NN / 128), 256, GEMM_SMEM>>>(x, qkv_w, qkv_b, nullptr);
    // KV projection (text): [512,1024] x [2048,1024]^T
    gemm_mma<1><<<dim3(2 * CC / 128, BB * MM / 128), 256, GEMM_SMEM>>>(y, kv_w, kv_b, nullptr);
    // RMSNorm q and k
    rmsnorm_kernel<0><<<(BB * HH * NN) / 8, 256>>>(qn_w);
    rmsnorm_kernel<1><<<(BB * HH * SS) / 8, 256>>>(kn_w);
    // Attention (tf32 tensor core)
    attn_mma<<<dim3(NN / 128, HH, BB), 256, ATTN_SMEM>>>();
    // Output projection -> d_out
    gemm_mma<2><<<dim3(CC / 128, BB * NN / 128), 256, GEMM_SMEM>>>(nullptr, proj_w, proj_b, out);
}

// round 5
// speedup vs baseline: 2.8989x; 1.2745x over previous
#include <cuda_runtime.h>
#include <cstdint>
#include <cstddef>

// Problem constants
#define BB   2
#define NN   2048
#define MM   256
#define CC   1024
#define HH   16
#define HD   64
#define SS   2304   // NN + MM

// Scratch (device globals: no allocation allowed)
__device__ float g_q [(size_t)BB * HH * NN * HD];   // [B,H,N,hd] (tf32 after rmsnorm)
__device__ float g_k [(size_t)BB * HH * SS * HD];   // [B,H,S,hd] (tf32 after rmsnorm)
__device__ float g_v [(size_t)BB * HH * SS * HD];   // [B,H,S,hd] (tf32)
__device__ float g_ao[(size_t)BB * NN * CC];        // [B,N,C] attn out (tf32)
// tf32-preconverted inputs
__device__ float g_xt [(size_t)BB * NN * CC];       // x
__device__ float g_yt [(size_t)BB * MM * CC];       // y
__device__ float g_wqkv[(size_t)3 * CC * CC];
__device__ float g_wkv [(size_t)2 * CC * CC];
__device__ float g_wp  [(size_t)CC * CC];

// ---------------------------------------------------------------------------
// helpers
// ---------------------------------------------------------------------------
__device__ __forceinline__ uint32_t smem_u32(const void* p) {
    uint32_t a;
    asm("{ .reg .u64 t; cvta.to.shared.u64 t, %1; cvt.u32.u64 %0, t; }"
        : "=r"(a) : "l"(p));
    return a;
}

__device__ __forceinline__ float tf32r(float x) {
    uint32_t u;
    asm("cvt.rna.tf32.f32 %0, %1;" : "=r"(u) : "f"(x));
    return __uint_as_float(u);
}

// raw-register m16n8k8 tf32 mma
__device__ __forceinline__ void mma_u(float* c, uint32_t a0, uint32_t a1,
                                      uint32_t a2, uint32_t a3,
                                      uint32_t b0, uint32_t b1) {
    asm volatile(
        "mma.sync.aligned.m16n8k8.row.col.f32.tf32.tf32.f32 "
        "{%0,%1,%2,%3}, {%4,%5,%6,%7}, {%8,%9}, {%0,%1,%2,%3};"
        : "+f"(c[0]), "+f"(c[1]), "+f"(c[2]), "+f"(c[3])
        : "r"(a0), "r"(a1), "r"(a2), "r"(a3), "r"(b0), "r"(b1));
}

__device__ __forceinline__ void mma_f2(float* c, float2 a01, float2 a23, float2 b) {
    mma_u(c, __float_as_uint(a01.x), __float_as_uint(a23.x),
             __float_as_uint(a01.y), __float_as_uint(a23.y),
             __float_as_uint(b.x), __float_as_uint(b.y));
}

#define LDSM4(r0, r1, r2, r3, addr)                                           \
    asm volatile("ldmatrix.sync.aligned.m8n8.x4.shared.b16 {%0,%1,%2,%3}, [%4];" \
                 : "=r"(r0), "=r"(r1), "=r"(r2), "=r"(r3) : "r"(addr))

#define CP16(smem_addr, gptr)                                                 \
    asm volatile("cp.async.cg.shared.global [%0], [%1], 16;"                  \
                 :: "r"(smem_addr), "l"(gptr) : "memory")
#define CP_COMMIT() asm volatile("cp.async.commit_group;" ::: "memory")
#define CP_WAIT1()  asm volatile("cp.async.wait_group 1;"  ::: "memory")

// ---------------------------------------------------------------------------
// tf32 pre-convert (elementwise, float4)
// ---------------------------------------------------------------------------
__global__ __launch_bounds__(256) void cvt_kernel(float* __restrict__ dst,
                                                  const float* __restrict__ src)
{
    const size_t i = ((size_t)blockIdx.x * 256 + threadIdx.x) * 4;
    float4 v = *(const float4*)(src + i);
    v.x = tf32r(v.x); v.y = tf32r(v.y); v.z = tf32r(v.z); v.w = tf32r(v.w);
    *(float4*)(dst + i) = v;
}

// ---------------------------------------------------------------------------
// GEMM: out[r,o] = sum_c A[r,c]*W[o,c] + bias[o]
// 128x128 tile, K-chunk 32, 3-stage cp.async, ldmatrix fragments, 8 warps 2x4.
// smem per stage: A[128][36] + B[128][36] floats (stride 36 -> LDSM conflict-free)
// ---------------------------------------------------------------------------
#define GSTR 36
#define GSTAGE (2 * 128 * GSTR)             // floats per stage (A+B)
#define GEMM_SMEM (3 * GSTAGE * 4)          // 110592 bytes

template <int MODE>
__global__ __launch_bounds__(256, 1) void gemm_mma(const float* __restrict__ bias,
                                                   float* __restrict__ outp)
{
    extern __shared__ float sm[];
    const uint32_t sbase = smem_u32(sm);

    const int tid  = threadIdx.x;
    const int lane = tid & 31;
    const int wid  = tid >> 5;
    const int wm   = wid >> 2;          // 0..1
    const int wn   = wid & 3;           // 0..3
    const int gid  = lane >> 2;
    const int tig  = lane & 3;

    const int rowBase = blockIdx.y * 128;
    const int colBase = blockIdx.x * 128;

    const float* Aptr = (MODE == 0) ? g_xt : (MODE == 1) ? g_yt : g_ao;
    const float* Wptr = (MODE == 0) ? g_wqkv : (MODE == 1) ? g_wkv : g_wp;

    // cp.async issue for one stage
    const int u_row = tid >> 3;          // base row for unit tid
    const int u_seg = tid & 7;

    auto issue_stage = [&](int stage, int k0) {
        const uint32_t aOff = sbase + (uint32_t)(stage * GSTAGE) * 4;
        const uint32_t bOff = aOff + 128 * GSTR * 4;
#pragma unroll
        for (int i = 0; i < 4; i++) {
            const int row = u_row + i * 32;
            const uint32_t d = (uint32_t)(row * GSTR + u_seg * 4) * 4;
            CP16(aOff + d, Aptr + (size_t)(rowBase + row) * CC + k0 + u_seg * 4);
            CP16(bOff + d, Wptr + (size_t)(colBase + row) * CC + k0 + u_seg * 4);
        }
        CP_COMMIT();
    };

    float c[4][4][4];
#pragma unroll
    for (int mt = 0; mt < 4; mt++)
#pragma unroll
        for (int nt = 0; nt < 4; nt++)
#pragma unroll
            for (int q = 0; q < 4; q++) c[mt][nt][q] = 0.f;

    issue_stage(0, 0);
    issue_stage(1, 32);

    // per-lane ldmatrix row components
    const int rA  = wm * 64 + (lane & 15);
    const int rB0 = wn * 32 + (lane & 15);
    const int segl = lane >> 4;

    for (int chunk = 0; chunk < 32; ++chunk) {
        CP_WAIT1();
        __syncthreads();

        if (chunk + 2 < 32) issue_stage((chunk + 2) % 3, (chunk + 2) * 32);
        else CP_COMMIT();   // empty group keeps wait_group bookkeeping uniform

        const int st = chunk % 3;
        const uint32_t aB = sbase + (uint32_t)(st * GSTAGE) * 4;
        const uint32_t bB = aB + 128 * GSTR * 4;

#pragma unroll
        for (int kk = 0; kk < 4; kk++) {
            const uint32_t sf = (uint32_t)((2 * kk + segl) * 4) * 4;
            uint32_t a[4][4];
#pragma unroll
            for (int mt = 0; mt < 4; mt++)
                LDSM4(a[mt][0], a[mt][1], a[mt][2], a[mt][3],
                      aB + (uint32_t)((rA + mt * 16) * GSTR) * 4 + sf);
            uint32_t b0, b1, b2, b3, b4, b5, b6, b7;
            LDSM4(b0, b1, b2, b3, bB + (uint32_t)(rB0 * GSTR) * 4 + sf);
            LDSM4(b4, b5, b6, b7, bB + (uint32_t)((rB0 + 16) * GSTR) * 4 + sf);
#pragma unroll
            for (int mt = 0; mt < 4; mt++) {
                mma_u(c[mt][0], a[mt][0], a[mt][1], a[mt][2], a[mt][3], b0, b2);
                mma_u(c[mt][1], a[mt][0], a[mt][1], a[mt][2], a[mt][3], b1, b3);
                mma_u(c[mt][2], a[mt][0], a[mt][1], a[mt][2], a[mt][3], b4, b6);
                mma_u(c[mt][3], a[mt][0], a[mt][1], a[mt][2], a[mt][3], b5, b7);
            }
        }
    }

    // epilogue: bias + scatter
    float2 bias2[4];
#pragma unroll
    for (int nt = 0; nt < 4; nt++) {
        const int col = colBase + wn * 32 + nt * 8 + tig * 2;
        bias2[nt] = *(const float2*)&bias[col];
    }

#pragma unroll
    for (int mt = 0; mt < 4; mt++)
#pragma unroll
        for (int nt = 0; nt < 4; nt++)
#pragma unroll
            for (int half = 0; half < 2; half++) {
                const int row = rowBase + wm * 64 + mt * 16 + gid + half * 8;
                const int col = colBase + wn * 32 + nt * 8 + tig * 2;
                float2 v;
                v.x = c[mt][nt][half * 2 + 0] + bias2[nt].x;
                v.y = c[mt][nt][half * 2 + 1] + bias2[nt].y;
                float* dst;
                bool isv = false;
                if (MODE == 0) {
                    const int b_ = row >> 11, n = row & (NN - 1);
                    const int t3 = col >> 10, h = (col >> 6) & 15, d = col & 63;
                    const size_t bh = (size_t)b_ * HH + h;
                    if (t3 == 0)      dst = g_q + (bh * NN + n) * HD + d;
                    else if (t3 == 1) dst = g_k + (bh * SS + n) * HD + d;
                    else            { dst = g_v + (bh * SS + n) * HD + d; isv = true; }
                } else if (MODE == 1) {
                    const int b_ = row >> 8, mm = row & (MM - 1);
                    const int t2 = col >> 10, h = (col >> 6) & 15, d = col & 63;
                    const size_t bh = (size_t)b_ * HH + h;
                    if (t2 == 0) dst = g_k + (bh * SS + NN + mm) * HD + d;
                    else       { dst = g_v + (bh * SS + NN + mm) * HD + d; isv = true; }
                } else {
                    dst = outp + (size_t)row * CC + col;
                }
                if (isv) { v.x = tf32r(v.x); v.y = tf32r(v.y); }
                *(float2*)dst = v;
            }
}

// ---------------------------------------------------------------------------
// RMSNorm over head_dim=64, q rows then k rows (merged); outputs tf32-rounded.
// ---------------------------------------------------------------------------
#define QROWS (BB * HH * NN)
#define KROWS (BB * HH * SS)

__global__ __launch_bounds__(256) void rmsnorm_kernel(const float* __restrict__ wq,
                                                      const float* __restrict__ wk)
{
    const int row  = blockIdx.x * 8 + (threadIdx.x >> 5);
    const int lane = threadIdx.x & 31;
    float* p;
    const float* w;
    if (row < QROWS) { p = g_q + (size_t)row * HD;           w = wq; }
    else             { p = g_k + (size_t)(row - QROWS) * HD; w = wk; }
    const float v0 = p[lane];
    const float v1 = p[lane + 32];
    float ss = v0 * v0 + v1 * v1;
#pragma unroll
    for (int o = 16; o; o >>= 1) ss += __shfl_xor_sync(0xffffffffu, ss, o);
    const float inv = rsqrtf(ss * (1.0f / 64.0f) + 1e-6f);
    p[lane]      = tf32r(v0 * inv * w[lane]);
    p[lane + 32] = tf32r(v1 * inv * w[lane + 32]);
}

// ---------------------------------------------------------------------------
// Tensor-core flash attention, cp.async 3-stage K/V, ldmatrix Q/K fragments.
// CTA: 128 queries x one (b,h); 8 warps x 16 rows; S-chunks of 64 (36 iters).
// smem floats: qs[128][68], ks[3][64][68], vs[3][64][72], ps[128][72]
// ---------------------------------------------------------------------------
#define QSTR 68
#define VSTR 72
#define KS_OFF  (128 * QSTR)
#define KSTAGE  (64 * QSTR)
#define VS_OFF  (KS_OFF + 3 * KSTAGE)
#define VSTAGE  (64 * VSTR)
#define PS_OFF  (VS_OFF + 3 * VSTAGE)
#define ATTN_SMEM ((PS_OFF + 128 * VSTR) * 4)   // 179200 bytes

__global__ __launch_bounds__(256, 1) void attn_mma()
{
    extern __shared__ float sm[];
    const uint32_t sbase = smem_u32(sm);
    float* qs = sm;
    float* ps = sm + PS_OFF;

    const int tid  = threadIdx.x;
    const int lane = tid & 31;
    const int wid  = tid >> 5;
    const int gid  = lane >> 2;
    const int tig  = lane & 3;

    const int qb = blockIdx.x * 128;
    const int h  = blockIdx.y;
    const int b  = blockIdx.z;
    const size_t bh = (size_t)b * HH + h;

    const float* qg = g_q + (bh * NN + qb) * HD;
    const float* kg = g_k + bh * SS * HD;
    const float* vg = g_v + bh * SS * HD;

    // cp.async one K/V stage (64 rows x 16 segs each)
    const int kv_row = tid >> 2;         // 0..63
    const int kv_seg = tid & 3;          // x4 strided below
    auto issue_stage = [&](int stage, int sc) {
        const uint32_t kOff = sbase + (uint32_t)(KS_OFF + stage * KSTAGE) * 4;
        const uint32_t vOff = sbase + (uint32_t)(VS_OFF + stage * VSTAGE) * 4;
#pragma unroll
        for (int i = 0; i < 4; i++) {
            const int seg = kv_seg + i * 4;
            CP16(kOff + (uint32_t)(kv_row * QSTR + seg * 4) * 4,
                 kg + (size_t)(sc + kv_row) * HD + seg * 4);
            CP16(vOff + (uint32_t)(kv_row * VSTR + seg * 4) * 4,
                 vg + (size_t)(sc + kv_row) * HD + seg * 4);
        }
        CP_COMMIT();
    };

    // load Q (plain, already tf32)
#pragma unroll
    for (int i = 0; i < 8; i++) {
        const int u = tid + 256 * i;
        const int row = u >> 4, c4 = (u & 15) * 4;
        *(float4*)&qs[row * QSTR + c4] = *(const float4*)&qg[(size_t)row * HD + c4];
    }

    issue_stage(0, 0);
    issue_stage(1, 64);

    float oacc[8][4];
#pragma unroll
    for (int nt = 0; nt < 8; nt++)
#pragma unroll
        for (int q = 0; q < 4; q++) oacc[nt][q] = 0.f;
    float m0 = -1e30f, m1 = -1e30f, l0 = 0.f, l1 = 0.f;
    const float scale = 0.125f;

    const int wrow = wid * 16;
    float* pw = ps + wrow * VSTR;
    const int pr0 = gid, pr1 = gid + 8;
    const int lrow = lane & 15;
    const int segl = lane >> 4;

    for (int c = 0; c < 36; ++c) {
        CP_WAIT1();
        __syncthreads();

        if (c + 2 < 36) issue_stage((c + 2) % 3, (c + 2) * 64);
        else CP_COMMIT();

        const int st = c % 3;
        const uint32_t ksB = sbase + (uint32_t)(KS_OFF + st * KSTAGE) * 4;
        const float* vsS = sm + VS_OFF + st * VSTAGE;

        // ---- phase 1: S = Q @ K^T ----
        float s[8][4];
#pragma unroll
        for (int nt = 0; nt < 8; nt++)
#pragma unroll
            for (int q = 0; q < 4; q++) s[nt][q] = 0.f;

#pragma unroll
        for (int kk = 0; kk < 8; kk++) {
            const uint32_t sf = (uint32_t)((2 * kk + segl) * 4) * 4;
            uint32_t a0, a1, a2, a3;
            LDSM4(a0, a1, a2, a3,
                  sbase + (uint32_t)((wrow + lrow) * QSTR) * 4 + sf);
#pragma unroll
            for (int p = 0; p < 4; p++) {
                uint32_t b0, b1, b2, b3;
                LDSM4(b0, b1, b2, b3,
                      ksB + (uint32_t)((p * 16 + lrow) * QSTR) * 4 + sf);
                mma_u(s[2 * p],     a0, a1, a2, a3, b0, b2);
                mma_u(s[2 * p + 1], a0, a1, a2, a3, b1, b3);
            }
        }

        // ---- online softmax ----
        float mx0 = -1e30f, mx1 = -1e30f;
#pragma unroll
        for (int nt = 0; nt < 8; nt++) {
            mx0 = fmaxf(mx0, fmaxf(s[nt][0], s[nt][1]));
            mx1 = fmaxf(mx1, fmaxf(s[nt][2], s[nt][3]));
        }
        mx0 = fmaxf(mx0, __shfl_xor_sync(0xffffffffu, mx0, 1));
        mx0 = fmaxf(mx0, __shfl_xor_sync(0xffffffffu, mx0, 2));
        mx1 = fmaxf(mx1, __shfl_xor_sync(0xffffffffu, mx1, 1));
        mx1 = fmaxf(mx1, __shfl_xor_sync(0xffffffffu, mx1, 2));

        const float mn0 = fmaxf(m0, mx0 * scale);
        const float mn1 = fmaxf(m1, mx1 * scale);
        const float cr0 = __expf(m0 - mn0);
        const float cr1 = __expf(m1 - mn1);
        m0 = mn0; m1 = mn1;

        float rs0 = 0.f, rs1 = 0.f;
#pragma unroll
        for (int nt = 0; nt < 8; nt++) {
            const float p00 = __expf(s[nt][0] * scale - mn0);
            const float p01 = __expf(s[nt][1] * scale - mn0);
            const float p10 = __expf(s[nt][2] * scale - mn1);
            const float p11 = __expf(s[nt][3] * scale - mn1);
            rs0 += p00 + p01;
            rs1 += p10 + p11;
            float2 w0; w0.x = tf32r(p00); w0.y = tf32r(p01);
            float2 w1; w1.x = tf32r(p10); w1.y = tf32r(p11);
            *(float2*)&pw[pr0 * VSTR + nt * 8 + tig * 2] = w0;
            *(float2*)&pw[pr1 * VSTR + nt * 8 + tig * 2] = w1;
        }
        rs0 += __shfl_xor_sync(0xffffffffu, rs0, 1);
        rs0 += __shfl_xor_sync(0xffffffffu, rs0, 2);
        rs1 += __shfl_xor_sync(0xffffffffu, rs1, 1);
        rs1 += __shfl_xor_sync(0xffffffffu, rs1, 2);
        l0 = l0 * cr0 + rs0;
        l1 = l1 * cr1 + rs1;
#pragma unroll
        for (int nt = 0; nt < 8; nt++) {
            oacc[nt][0] *= cr0; oacc[nt][1] *= cr0;
            oacc[nt][2] *= cr1; oacc[nt][3] *= cr1;
        }
        __syncwarp();

        // ---- phase 2: O += P @ V ----
#pragma unroll
        for (int kk = 0; kk < 8; kk++) {
            float2 a0, a1;
            a0.x = pw[pr0 * VSTR + kk * 8 + tig];
            a0.y = pw[pr0 * VSTR + kk * 8 + tig + 4];
            a1.x = pw[pr1 * VSTR + kk * 8 + tig];
            a1.y = pw[pr1 * VSTR + kk * 8 + tig + 4];
#pragma unroll
            for (int nt = 0; nt < 8; nt++) {
                float2 bv;
                bv.x = vsS[(kk * 8 + tig) * VSTR + nt * 8 + gid];
                bv.y = vsS[(kk * 8 + tig + 4) * VSTR + nt * 8 + gid];
                mma_f2(oacc[nt], a0, a1, bv);
            }
        }
    }

    // epilogue: normalize, tf32-round, write [B,N,C]
    const float inv0 = 1.0f / l0;
    const float inv1 = 1.0f / l1;
    const int n0 = qb + wrow + gid;
    const int n1 = n0 + 8;
#pragma unroll
    for (int nt = 0; nt < 8; nt++) {
        const int d = h * HD + nt * 8 + tig * 2;
        float2 v0, v1;
        v0.x = tf32r(oacc[nt][0] * inv0); v0.y = tf32r(oacc[nt][1] * inv0);
        v1.x = tf32r(oacc[nt][2] * inv1); v1.y = tf32r(oacc[nt][3] * inv1);
        *(float2*)&g_ao[((size_t)b * NN + n0) * CC + d] = v0;
        *(float2*)&g_ao[((size_t)b * NN + n1) * CC + d] = v1;
    }
}

// ---------------------------------------------------------------------------
extern "C" void kernel_launch(void* const* d_in, const int* in_sizes, int n_in,
                              void* d_out, int out_size)
{
    const float* x      = (const float*)d_in[0];
    const float* y      = (const float*)d_in[1];
    const float* qkv_w  = (const float*)d_in[2];
    const float* qkv_b  = (const float*)d_in[3];
    const float* kv_w   = (const float*)d_in[4];
    const float* kv_b   = (const float*)d_in[5];
    const float* qn_w   = (const float*)d_in[6];
    const float* kn_w   = (const float*)d_in[7];
    const float* proj_w = (const float*)d_in[8];
    const float* proj_b = (const float*)d_in[9];
    float* out = (float*)d_out;

    (void)in_sizes; (void)n_in; (void)out_size;

    cudaFuncSetAttribute(gemm_mma<0>, cudaFuncAttributeMaxDynamicSharedMemorySize, GEMM_SMEM);
    cudaFuncSetAttribute(gemm_mma<1>, cudaFuncAttributeMaxDynamicSharedMemorySize, GEMM_SMEM);
    cudaFuncSetAttribute(gemm_mma<2>, cudaFuncAttributeMaxDynamicSharedMemorySize, GEMM_SMEM);
    cudaFuncSetAttribute(attn_mma, cudaFuncAttributeMaxDynamicSharedMemorySize, ATTN_SMEM);

    float* d_xt;   cudaGetSymbolAddress((void**)&d_xt,  g_xt);
    float* d_yt;   cudaGetSymbolAddress((void**)&d_yt,  g_yt);
    float* d_wqkv; cudaGetSymbolAddress((void**)&d_wqkv, g_wqkv);
    float* d_wkv;  cudaGetSymbolAddress((void**)&d_wkv, g_wkv);
    float* d_wp;   cudaGetSymbolAddress((void**)&d_wp,  g_wp);

    // pre-convert inputs to tf32 (RNA) once
    cvt_kernel<<<(BB * NN * CC) / 1024, 256>>>(d_xt, x);
    cvt_kernel<<<(BB * MM * CC) / 1024, 256>>>(d_yt, y);
    cvt_kernel<<<(3 * CC * CC) / 1024, 256>>>(d_wqkv, qkv_w);
    cvt_kernel<<<(2 * CC * CC) / 1024, 256>>>(d_wkv, kv_w);
    cvt_kernel<<<(CC * CC) / 1024, 256>>>(d_wp, proj_w);

    // QKV projection (image)
    gemm_mma<0><<<dim3(3 * CC / 128, BB * NN / 128), 256, GEMM_SMEM>>>(qkv_b, nullptr);
    // KV projection (text)
    gemm_mma<1><<<dim3(2 * CC / 128, BB * MM / 128), 256, GEMM_SMEM>>>(kv_b, nullptr);
    // RMSNorm q + k (merged, tf32 outputs)
    rmsnorm_kernel<<<(QROWS + KROWS) / 8, 256>>>(qn_w, kn_w);
    // Attention (tf32 tensor core, cp.async pipelined)
    attn_mma<<<dim3(NN / 128, HH, BB), 256, ATTN_SMEM>>>();
    // Output projection -> d_out (fp32 result)
    gemm_mma<2><<<dim3(CC / 128, BB * NN / 128), 256, GEMM_SMEM>>>(proj_b, out);
}

// round 6
// speedup vs baseline: 4.9185x; 1.6967x over previous
#include <cuda_runtime.h>
#include <cuda_fp16.h>
#include <cstdint>
#include <cstddef>

// Problem constants
#define BB   2
#define NN   2048
#define MM   256
#define CC   1024
#define HH   16
#define HD   64
#define SS   2304   // NN + MM

// Scratch (device globals; fp16 activations)
__device__ __half g_q [(size_t)BB * HH * NN * HD];   // [B,H,N,hd] (rms-normed, x0.125)
__device__ __half g_k [(size_t)BB * HH * SS * HD];   // [B,H,S,hd] (rms-normed)
__device__ __half g_v [(size_t)BB * HH * SS * HD];   // [B,H,S,hd]
__device__ __half g_ao[(size_t)BB * NN * CC];        // [B,N,C] attn out
// fp16-preconverted inputs
__device__ __half g_xh  [(size_t)BB * NN * CC];
__device__ __half g_yh  [(size_t)BB * MM * CC];
__device__ __half g_wqkv[(size_t)3 * CC * CC];
__device__ __half g_wkv [(size_t)2 * CC * CC];
__device__ __half g_wp  [(size_t)CC * CC];

// ---------------------------------------------------------------------------
// helpers
// ---------------------------------------------------------------------------
__device__ __forceinline__ uint32_t smem_u32(const void* p) {
    uint32_t a;
    asm("{ .reg .u64 t; cvta.to.shared.u64 t, %1; cvt.u32.u64 %0, t; }"
        : "=r"(a) : "l"(p));
    return a;
}

// m16n8k16 fp16 mma, fp32 accumulate
__device__ __forceinline__ void mma_h(float* c, uint32_t a0, uint32_t a1,
                                      uint32_t a2, uint32_t a3,
                                      uint32_t b0, uint32_t b1) {
    asm volatile(
        "mma.sync.aligned.m16n8k16.row.col.f32.f16.f16.f32 "
        "{%0,%1,%2,%3}, {%4,%5,%6,%7}, {%8,%9}, {%0,%1,%2,%3};"
        : "+f"(c[0]), "+f"(c[1]), "+f"(c[2]), "+f"(c[3])
        : "r"(a0), "r"(a1), "r"(a2), "r"(a3), "r"(b0), "r"(b1));
}

#define LDSM4(r0, r1, r2, r3, addr)                                           \
    asm volatile("ldmatrix.sync.aligned.m8n8.x4.shared.b16 {%0,%1,%2,%3}, [%4];" \
                 : "=r"(r0), "=r"(r1), "=r"(r2), "=r"(r3) : "r"(addr))
#define LDSM4T(r0, r1, r2, r3, addr)                                          \
    asm volatile("ldmatrix.sync.aligned.m8n8.x4.trans.shared.b16 {%0,%1,%2,%3}, [%4];" \
                 : "=r"(r0), "=r"(r1), "=r"(r2), "=r"(r3) : "r"(addr))

#define CP16(smem_addr, gptr)                                                 \
    asm volatile("cp.async.cg.shared.global [%0], [%1], 16;"                  \
                 :: "r"(smem_addr), "l"(gptr) : "memory")
#define CP_COMMIT() asm volatile("cp.async.commit_group;" ::: "memory")
#define CP_WAIT1()  asm volatile("cp.async.wait_group 1;"  ::: "memory")

// ---------------------------------------------------------------------------
// fp32 -> fp16 pre-convert
// ---------------------------------------------------------------------------
__global__ __launch_bounds__(256) void cvt_kernel(__half* __restrict__ dst,
                                                  const float* __restrict__ src)
{
    const size_t i = ((size_t)blockIdx.x * 256 + threadIdx.x) * 4;
    float4 v = *(const float4*)(src + i);
    __half2 h0 = __floats2half2_rn(v.x, v.y);
    __half2 h1 = __floats2half2_rn(v.z, v.w);
    uint2 u;
    u.x = *reinterpret_cast<uint32_t*>(&h0);
    u.y = *reinterpret_cast<uint32_t*>(&h1);
    *(uint2*)(dst + i) = u;
}

// ---------------------------------------------------------------------------
// fp16 NT GEMM: out[r,o] = sum_c A[r,c]*W[o,c] + bias[o]
// 128x128 tile, K-chunk 64, 3-stage cp.async, ldmatrix, m16n8k16 mma.
// smem per stage: A[128][72] + B[128][72] halves (stride 144B, LDSM clean).
// ---------------------------------------------------------------------------
#define GSTR 72
#define GSTAGE (2 * 128 * GSTR)            // halves per stage
#define GEMM_SMEM (3 * GSTAGE * 2)         // 110592 bytes

template <int MODE>
__global__ __launch_bounds__(256, 1) void gemm_mma(const float* __restrict__ bias,
                                                   float* __restrict__ outp)
{
    extern __shared__ __half smh[];
    const uint32_t sbase = smem_u32(smh);

    const int tid  = threadIdx.x;
    const int lane = tid & 31;
    const int wid  = tid >> 5;
    const int wm   = wid >> 2;
    const int wn   = wid & 3;
    const int gid  = lane >> 2;
    const int tig  = lane & 3;

    const int rowBase = blockIdx.y * 128;
    const int colBase = blockIdx.x * 128;

    const __half* Aptr = (MODE == 0) ? g_xh : (MODE == 1) ? g_yh : g_ao;
    const __half* Wptr = (MODE == 0) ? g_wqkv : (MODE == 1) ? g_wkv : g_wp;

    const int u_row = tid >> 1;          // 0..127
    const int u_s4  = (tid & 1) * 4;

    auto issue_stage = [&](int stage, int k0) {
        const uint32_t aOff = sbase + (uint32_t)(stage * GSTAGE) * 2;
        const uint32_t bOff = aOff + 128 * GSTR * 2;
#pragma unroll
        for (int i = 0; i < 4; i++) {
            const int seg = u_s4 + i;
            const uint32_t d = (uint32_t)(u_row * GSTR + seg * 8) * 2;
            CP16(aOff + d, Aptr + (size_t)(rowBase + u_row) * CC + k0 + seg * 8);
            CP16(bOff + d, Wptr + (size_t)(colBase + u_row) * CC + k0 + seg * 8);
        }
        CP_COMMIT();
    };

    float c[4][4][4];
#pragma unroll
    for (int mt = 0; mt < 4; mt++)
#pragma unroll
        for (int nt = 0; nt < 4; nt++)
#pragma unroll
            for (int q = 0; q < 4; q++) c[mt][nt][q] = 0.f;

    issue_stage(0, 0);
    issue_stage(1, 64);

    const int lr8  = lane & 7;
    const int aRow = (lane >> 3) & 1;
    const int aCol = lane >> 4;

    for (int chunk = 0; chunk < 16; ++chunk) {
        CP_WAIT1();
        __syncthreads();

        if (chunk + 2 < 16) issue_stage((chunk + 2) % 3, (chunk + 2) * 64);
        else CP_COMMIT();

        const int st = chunk % 3;
        const uint32_t aB = sbase + (uint32_t)(st * GSTAGE) * 2;
        const uint32_t bB = aB + 128 * GSTR * 2;

#pragma unroll
        for (int kk = 0; kk < 4; kk++) {
            uint32_t a[4][4];
#pragma unroll
            for (int mt = 0; mt < 4; mt++)
                LDSM4(a[mt][0], a[mt][1], a[mt][2], a[mt][3],
                      aB + (uint32_t)((wm * 64 + mt * 16 + lr8 + aRow * 8) * GSTR
                                      + kk * 16 + aCol * 8) * 2);
#pragma unroll
            for (int p = 0; p < 2; p++) {
                uint32_t b0, b1, b2, b3;
                LDSM4(b0, b1, b2, b3,
                      bB + (uint32_t)((wn * 32 + p * 16 + lr8 + aCol * 8) * GSTR
                                      + kk * 16 + aRow * 8) * 2);
#pragma unroll
                for (int mt = 0; mt < 4; mt++) {
                    mma_h(c[mt][2 * p],     a[mt][0], a[mt][1], a[mt][2], a[mt][3], b0, b1);
                    mma_h(c[mt][2 * p + 1], a[mt][0], a[mt][1], a[mt][2], a[mt][3], b2, b3);
                }
            }
        }
    }

    // epilogue: bias + scatter
    float2 bias2[4];
#pragma unroll
    for (int nt = 0; nt < 4; nt++) {
        const int col = colBase + wn * 32 + nt * 8 + tig * 2;
        bias2[nt] = *(const float2*)&bias[col];
    }

#pragma unroll
    for (int mt = 0; mt < 4; mt++)
#pragma unroll
        for (int nt = 0; nt < 4; nt++)
#pragma unroll
            for (int half_ = 0; half_ < 2; half_++) {
                const int row = rowBase + wm * 64 + mt * 16 + gid + half_ * 8;
                const int col = colBase + wn * 32 + nt * 8 + tig * 2;
                const float vx = c[mt][nt][half_ * 2 + 0] + bias2[nt].x;
                const float vy = c[mt][nt][half_ * 2 + 1] + bias2[nt].y;
                if (MODE == 2) {
                    float2 v; v.x = vx; v.y = vy;
                    *(float2*)(outp + (size_t)row * CC + col) = v;
                } else {
                    __half* dst;
                    if (MODE == 0) {
                        const int b_ = row >> 11, n = row & (NN - 1);
                        const int t3 = col >> 10, h = (col >> 6) & 15, d = col & 63;
                        const size_t bh = (size_t)b_ * HH + h;
                        if (t3 == 0)      dst = g_q + (bh * NN + n) * HD + d;
                        else if (t3 == 1) dst = g_k + (bh * SS + n) * HD + d;
                        else              dst = g_v + (bh * SS + n) * HD + d;
                    } else {
                        const int b_ = row >> 8, mm = row & (MM - 1);
                        const int t2 = col >> 10, h = (col >> 6) & 15, d = col & 63;
                        const size_t bh = (size_t)b_ * HH + h;
                        dst = (t2 == 0) ? g_k + (bh * SS + NN + mm) * HD + d
                                        : g_v + (bh * SS + NN + mm) * HD + d;
                    }
                    __half2 hv = __floats2half2_rn(vx, vy);
                    *(__half2*)dst = hv;
                }
            }
}

// ---------------------------------------------------------------------------
// RMSNorm over head_dim=64 (fp16 in/out). q rows get x0.125 scale folded in.
// ---------------------------------------------------------------------------
#define QROWS (BB * HH * NN)
#define KROWS (BB * HH * SS)

__global__ __launch_bounds__(256) void rmsnorm_kernel(const float* __restrict__ wq,
                                                      const float* __restrict__ wk)
{
    const int row  = blockIdx.x * 8 + (threadIdx.x >> 5);
    const int lane = threadIdx.x & 31;
    const bool isq = row < QROWS;
    __half2* p = isq ? (__half2*)g_q + (size_t)row * 32
                     : (__half2*)g_k + (size_t)(row - QROWS) * 32;
    const float* w = isq ? wq : wk;
    const float2 f = __half22float2(p[lane]);
    float ss = f.x * f.x + f.y * f.y;
#pragma unroll
    for (int o = 16; o; o >>= 1) ss += __shfl_xor_sync(0xffffffffu, ss, o);
    float inv = rsqrtf(ss * (1.0f / 64.0f) + 1e-6f);
    if (isq) inv *= 0.125f;    // fold attention scale into q
    p[lane] = __floats2half2_rn(f.x * inv * w[2 * lane], f.y * inv * w[2 * lane + 1]);
}

// ---------------------------------------------------------------------------
// fp16 tensor-core flash attention, fixed-shift softmax (|logit| <= 8).
// CTA: 128 queries x (b,h); 8 warps x 16 q rows; S-chunks of 64 (36 iters).
// smem halves: qs[128][72], ks[3][64][72], vs[3][64][72], ps[128][72]
// ---------------------------------------------------------------------------
#define ASTR 72
#define KS_OFF (128 * ASTR)
#define KSTG   (64 * ASTR)
#define VS_OFF (KS_OFF + 3 * KSTG)
#define PS_OFF (VS_OFF + 3 * KSTG)
#define ATTN_SMEM ((PS_OFF + 128 * ASTR) * 2)   // 92160 bytes

__global__ __launch_bounds__(256, 2) void attn_mma()
{
    extern __shared__ __half sh[];
    const uint32_t sbase = smem_u32(sh);
    __half* ps = sh + PS_OFF;

    const int tid  = threadIdx.x;
    const int lane = tid & 31;
    const int wid  = tid >> 5;
    const int gid  = lane >> 2;
    const int tig  = lane & 3;
    const int lr8  = lane & 7;
    const int aRow = (lane >> 3) & 1;
    const int aCol = lane >> 4;

    const int qb = blockIdx.x * 128;
    const int h  = blockIdx.y;
    const int b  = blockIdx.z;
    const size_t bh = (size_t)b * HH + h;

    const __half* qg = g_q + (bh * NN + qb) * HD;
    const __half* kg = g_k + bh * SS * HD;
    const __half* vg = g_v + bh * SS * HD;

    // load Q (fp16, 16B units)
#pragma unroll
    for (int i = 0; i < 4; i++) {
        const int u = tid + 256 * i;
        const int row = u >> 3, seg = u & 7;
        *(uint4*)&sh[row * ASTR + seg * 8] = *(const uint4*)&qg[(size_t)row * HD + seg * 8];
    }

    const int kv_row = tid >> 2;
    const int kv_sg  = tid & 3;
    auto issue_stage = [&](int stage, int sc) {
        const uint32_t kOff = sbase + (uint32_t)(KS_OFF + stage * KSTG) * 2;
        const uint32_t vOff = sbase + (uint32_t)(VS_OFF + stage * KSTG) * 2;
#pragma unroll
        for (int i = 0; i < 2; i++) {
            const int seg = kv_sg * 2 + i;
            const uint32_t d = (uint32_t)(kv_row * ASTR + seg * 8) * 2;
            CP16(kOff + d, kg + (size_t)(sc + kv_row) * HD + seg * 8);
            CP16(vOff + d, vg + (size_t)(sc + kv_row) * HD + seg * 8);
        }
        CP_COMMIT();
    };

    issue_stage(0, 0);
    issue_stage(1, 64);

    float oacc[8][4];
#pragma unroll
    for (int nt = 0; nt < 8; nt++)
#pragma unroll
        for (int q = 0; q < 4; q++) oacc[nt][q] = 0.f;
    float l0 = 0.f, l1 = 0.f;

    const int wrow = wid * 16;
    const int pr0 = wrow + gid, pr1 = pr0 + 8;

    for (int c = 0; c < 36; ++c) {
        CP_WAIT1();
        __syncthreads();

        if (c + 2 < 36) issue_stage((c + 2) % 3, (c + 2) * 64);
        else CP_COMMIT();

        const int st = c % 3;
        const uint32_t ksB = sbase + (uint32_t)(KS_OFF + st * KSTG) * 2;
        const uint32_t vsB = sbase + (uint32_t)(VS_OFF + st * KSTG) * 2;
        const uint32_t psB = sbase + (uint32_t)PS_OFF * 2;

        // ---- S = Q @ K^T (q pre-scaled; logits bounded by 8) ----
        float s[8][4];
#pragma unroll
        for (int nt = 0; nt < 8; nt++)
#pragma unroll
            for (int q = 0; q < 4; q++) s[nt][q] = 0.f;

#pragma unroll
        for (int kk = 0; kk < 4; kk++) {
            uint32_t a0, a1, a2, a3;
            LDSM4(a0, a1, a2, a3,
                  sbase + (uint32_t)((wrow + lr8 + aRow * 8) * ASTR
                                     + kk * 16 + aCol * 8) * 2);
#pragma unroll
            for (int p = 0; p < 4; p++) {
                uint32_t b0, b1, b2, b3;
                LDSM4(b0, b1, b2, b3,
                      ksB + (uint32_t)((p * 16 + lr8 + aCol * 8) * ASTR
                                       + kk * 16 + aRow * 8) * 2);
                mma_h(s[2 * p],     a0, a1, a2, a3, b0, b1);
                mma_h(s[2 * p + 1], a0, a1, a2, a3, b2, b3);
            }
        }

        // ---- fixed-shift softmax: p = exp(s - 8), sums deferred ----
        float rs0 = 0.f, rs1 = 0.f;
#pragma unroll
        for (int nt = 0; nt < 8; nt++) {
            const float p00 = __expf(s[nt][0] - 8.0f);
            const float p01 = __expf(s[nt][1] - 8.0f);
            const float p10 = __expf(s[nt][2] - 8.0f);
            const float p11 = __expf(s[nt][3] - 8.0f);
            rs0 += p00 + p01;
            rs1 += p10 + p11;
            *(__half2*)&ps[pr0 * ASTR + nt * 8 + tig * 2] = __floats2half2_rn(p00, p01);
            *(__half2*)&ps[pr1 * ASTR + nt * 8 + tig * 2] = __floats2half2_rn(p10, p11);
        }
        l0 += rs0;
        l1 += rs1;
        __syncwarp();

        // ---- O += P @ V ----
#pragma unroll
        for (int kk = 0; kk < 4; kk++) {
            uint32_t a0, a1, a2, a3;
            LDSM4(a0, a1, a2, a3,
                  psB + (uint32_t)((wrow + lr8 + aRow * 8) * ASTR
                                   + kk * 16 + aCol * 8) * 2);
#pragma unroll
            for (int p = 0; p < 4; p++) {
                uint32_t b0, b1, b2, b3;
                LDSM4T(b0, b1, b2, b3,
                       vsB + (uint32_t)((kk * 16 + lr8 + aRow * 8) * ASTR
                                        + p * 16 + aCol * 8) * 2);
                mma_h(oacc[2 * p],     a0, a1, a2, a3, b0, b1);
                mma_h(oacc[2 * p + 1], a0, a1, a2, a3, b2, b3);
            }
        }
        __syncwarp();
    }

    // ---- epilogue: reduce l over quad, normalize, write fp16 ----
    l0 += __shfl_xor_sync(0xffffffffu, l0, 1);
    l0 += __shfl_xor_sync(0xffffffffu, l0, 2);
    l1 += __shfl_xor_sync(0xffffffffu, l1, 1);
    l1 += __shfl_xor_sync(0xffffffffu, l1, 2);
    const float inv0 = 1.0f / l0;
    const float inv1 = 1.0f / l1;
    const int n0 = qb + wrow + gid;
    const int n1 = n0 + 8;
#pragma unroll
    for (int nt = 0; nt < 8; nt++) {
        const int d = h * HD + nt * 8 + tig * 2;
        *(__half2*)&g_ao[((size_t)b * NN + n0) * CC + d] =
            __floats2half2_rn(oacc[nt][0] * inv0, oacc[nt][1] * inv0);
        *(__half2*)&g_ao[((size_t)b * NN + n1) * CC + d] =
            __floats2half2_rn(oacc[nt][2] * inv1, oacc[nt][3] * inv1);
    }
}

// ---------------------------------------------------------------------------
extern "C" void kernel_launch(void* const* d_in, const int* in_sizes, int n_in,
                              void* d_out, int out_size)
{
    const float* x      = (const float*)d_in[0];
    const float* y      = (const float*)d_in[1];
    const float* qkv_w  = (const float*)d_in[2];
    const float* qkv_b  = (const float*)d_in[3];
    const float* kv_w   = (const float*)d_in[4];
    const float* kv_b   = (const float*)d_in[5];
    const float* qn_w   = (const float*)d_in[6];
    const float* kn_w   = (const float*)d_in[7];
    const float* proj_w = (const float*)d_in[8];
    const float* proj_b = (const float*)d_in[9];
    float* out = (float*)d_out;

    (void)in_sizes; (void)n_in; (void)out_size;

    cudaFuncSetAttribute(gemm_mma<0>, cudaFuncAttributeMaxDynamicSharedMemorySize, GEMM_SMEM);
    cudaFuncSetAttribute(gemm_mma<1>, cudaFuncAttributeMaxDynamicSharedMemorySize, GEMM_SMEM);
    cudaFuncSetAttribute(gemm_mma<2>, cudaFuncAttributeMaxDynamicSharedMemorySize, GEMM_SMEM);
    cudaFuncSetAttribute(attn_mma, cudaFuncAttributeMaxDynamicSharedMemorySize, ATTN_SMEM);

    __half* d_xh;   cudaGetSymbolAddress((void**)&d_xh,   g_xh);
    __half* d_yh;   cudaGetSymbolAddress((void**)&d_yh,   g_yh);
    __half* d_wqkv; cudaGetSymbolAddress((void**)&d_wqkv, g_wqkv);
    __half* d_wkv;  cudaGetSymbolAddress((void**)&d_wkv,  g_wkv);
    __half* d_wp;   cudaGetSymbolAddress((void**)&d_wp,   g_wp);

    // pre-convert inputs/weights to fp16 once
    cvt_kernel<<<(BB * NN * CC) / 1024, 256>>>(d_xh, x);
    cvt_kernel<<<(BB * MM * CC) / 1024, 256>>>(d_yh, y);
    cvt_kernel<<<(3 * CC * CC) / 1024, 256>>>(d_wqkv, qkv_w);
    cvt_kernel<<<(2 * CC * CC) / 1024, 256>>>(d_wkv, kv_w);
    cvt_kernel<<<(CC * CC) / 1024, 256>>>(d_wp, proj_w);

    // QKV projection (image)
    gemm_mma<0><<<dim3(3 * CC / 128, BB * NN / 128), 256, GEMM_SMEM>>>(qkv_b, nullptr);
    // KV projection (text)
    gemm_mma<1><<<dim3(2 * CC / 128, BB * MM / 128), 256, GEMM_SMEM>>>(kv_b, nullptr);
    // RMSNorm q (+0.125 scale) and k
    rmsnorm_kernel<<<(QROWS + KROWS) / 8, 256>>>(qn_w, kn_w);
    // Attention (fp16 mma, fixed-shift softmax)
    attn_mma<<<dim3(NN / 128, HH, BB), 256, ATTN_SMEM>>>();
    // Output projection -> d_out (fp32 + bias)
    gemm_mma<2><<<dim3(CC / 128, BB * NN / 128), 256, GEMM_SMEM>>>(proj_b, out);
}

// round 8
// speedup vs baseline: 5.7380x; 1.1666x over previous
#include <cuda_runtime.h>
#include <cuda_fp16.h>
#include <cstdint>
#include <cstddef>

// Problem constants
#define BB   2
#define NN   2048
#define MM   256
#define CC   1024
#define HH   16
#define HD   64
#define SS   2304   // NN + MM

// Scratch (device globals; fp16 activations)
__device__ __half g_q [(size_t)BB * HH * NN * HD];   // [B,H,N,hd] (rms-normed, x0.125)
__device__ __half g_k [(size_t)BB * HH * SS * HD];   // [B,H,S,hd] (rms-normed)
__device__ __half g_v [(size_t)BB * HH * SS * HD];   // [B,H,S,hd]
__device__ __half g_ao[(size_t)BB * NN * CC];        // [B,N,C] attn out
// fp16-preconverted inputs
__device__ __half g_xh  [(size_t)BB * NN * CC];
__device__ __half g_yh  [(size_t)BB * MM * CC];
__device__ __half g_wqkv[(size_t)3 * CC * CC];
__device__ __half g_wkv [(size_t)2 * CC * CC];
__device__ __half g_wp  [(size_t)CC * CC];

// ---------------------------------------------------------------------------
// helpers
// ---------------------------------------------------------------------------
__device__ __forceinline__ uint32_t smem_u32(const void* p) {
    uint32_t a;
    asm("{ .reg .u64 t; cvta.to.shared.u64 t, %1; cvt.u32.u64 %0, t; }"
        : "=r"(a) : "l"(p));
    return a;
}

// m16n8k16 fp16 mma, fp32 accumulate
__device__ __forceinline__ void mma_h(float* c, uint32_t a0, uint32_t a1,
                                      uint32_t a2, uint32_t a3,
                                      uint32_t b0, uint32_t b1) {
    asm volatile(
        "mma.sync.aligned.m16n8k16.row.col.f32.f16.f16.f32 "
        "{%0,%1,%2,%3}, {%4,%5,%6,%7}, {%8,%9}, {%0,%1,%2,%3};"
        : "+f"(c[0]), "+f"(c[1]), "+f"(c[2]), "+f"(c[3])
        : "r"(a0), "r"(a1), "r"(a2), "r"(a3), "r"(b0), "r"(b1));
}

__device__ __forceinline__ uint32_t pack_h2(float x, float y) {
    __half2 h = __floats2half2_rn(x, y);
    return *reinterpret_cast<uint32_t*>(&h);
}

#define LDSM4(r0, r1, r2, r3, addr)                                           \
    asm volatile("ldmatrix.sync.aligned.m8n8.x4.shared.b16 {%0,%1,%2,%3}, [%4];" \
                 : "=r"(r0), "=r"(r1), "=r"(r2), "=r"(r3) : "r"(addr))
#define LDSM4T(r0, r1, r2, r3, addr)                                          \
    asm volatile("ldmatrix.sync.aligned.m8n8.x4.trans.shared.b16 {%0,%1,%2,%3}, [%4];" \
                 : "=r"(r0), "=r"(r1), "=r"(r2), "=r"(r3) : "r"(addr))

#define CP16(smem_addr, gptr)                                                 \
    asm volatile("cp.async.cg.shared.global [%0], [%1], 16;"                  \
                 :: "r"(smem_addr), "l"(gptr) : "memory")
#define CP_COMMIT() asm volatile("cp.async.commit_group;" ::: "memory")
#define CP_WAIT1()  asm volatile("cp.async.wait_group 1;"  ::: "memory")

// ---------------------------------------------------------------------------
// merged fp32 -> fp16 pre-convert (x | y | qkv_w | kv_w | proj_w), one launch
// block = 1024 elems. segment blocks: x 4096, y 512, wqkv 3072, wkv 2048, wp 1024
// ---------------------------------------------------------------------------
#define XB  ((BB * NN * CC) / 1024)        // 4096
#define YB  ((BB * MM * CC) / 1024)        // 512
#define W3B ((3 * CC * CC) / 1024)         // 3072
#define W2B ((2 * CC * CC) / 1024)         // 2048
#define W1B ((CC * CC) / 1024)             // 1024
#define CVT_BLOCKS (XB + YB + W3B + W2B + W1B)

__global__ __launch_bounds__(256) void cvt_all(const float* __restrict__ x,
                                               const float* __restrict__ y,
                                               const float* __restrict__ wqkv,
                                               const float* __restrict__ wkv,
                                               const float* __restrict__ wp)
{
    int blk = blockIdx.x;
    const float* src;
    __half* dst;
    if (blk < XB)                    { src = x;    dst = g_xh; }
    else if ((blk -= XB) < YB)       { src = y;    dst = g_yh; }
    else if ((blk -= YB) < W3B)      { src = wqkv; dst = g_wqkv; }
    else if ((blk -= W3B) < W2B)     { src = wkv;  dst = g_wkv; }
    else                             { blk -= W2B; src = wp; dst = g_wp; }
    const size_t i = ((size_t)blk * 256 + threadIdx.x) * 4;
    float4 v = *(const float4*)(src + i);
    uint2 u;
    u.x = pack_h2(v.x, v.y);
    u.y = pack_h2(v.z, v.w);
    *(uint2*)(dst + i) = u;
}

// ---------------------------------------------------------------------------
// fp16 NT GEMM: out[r,o] = sum_c A[r,c]*W[o,c] + bias[o]
// 128x128 tile, K-chunk 64, 3-stage cp.async, ldmatrix, m16n8k16 mma.
// ---------------------------------------------------------------------------
#define GSTR 72
#define GSTAGE (2 * 128 * GSTR)            // halves per stage
#define GEMM_SMEM (3 * GSTAGE * 2)         // 110592 bytes

template <int MODE>
__global__ __launch_bounds__(256, 2) void gemm_mma(const float* __restrict__ bias,
                                                   float* __restrict__ outp)
{
    extern __shared__ __half smh[];
    const uint32_t sbase = smem_u32(smh);

    const int tid  = threadIdx.x;
    const int lane = tid & 31;
    const int wid  = tid >> 5;
    const int wm   = wid >> 2;
    const int wn   = wid & 3;
    const int gid  = lane >> 2;
    const int tig  = lane & 3;

    const int rowBase = blockIdx.y * 128;
    const int colBase = blockIdx.x * 128;

    const __half* Aptr = (MODE == 0) ? g_xh : (MODE == 1) ? g_yh : g_ao;
    const __half* Wptr = (MODE == 0) ? g_wqkv : (MODE == 1) ? g_wkv : g_wp;

    const int u_row = tid >> 1;          // 0..127
    const int u_s4  = (tid & 1) * 4;

    auto issue_stage = [&](int stage, int k0) {
        const uint32_t aOff = sbase + (uint32_t)(stage * GSTAGE) * 2;
        const uint32_t bOff = aOff + 128 * GSTR * 2;
#pragma unroll
        for (int i = 0; i < 4; i++) {
            const int seg = u_s4 + i;
            const uint32_t d = (uint32_t)(u_row * GSTR + seg * 8) * 2;
            CP16(aOff + d, Aptr + (size_t)(rowBase + u_row) * CC + k0 + seg * 8);
            CP16(bOff + d, Wptr + (size_t)(colBase + u_row) * CC + k0 + seg * 8);
        }
        CP_COMMIT();
    };

    float c[4][4][4];
#pragma unroll
    for (int mt = 0; mt < 4; mt++)
#pragma unroll
        for (int nt = 0; nt < 4; nt++)
#pragma unroll
            for (int q = 0; q < 4; q++) c[mt][nt][q] = 0.f;

    issue_stage(0, 0);
    issue_stage(1, 64);

    const int lr8  = lane & 7;
    const int aRow = (lane >> 3) & 1;
    const int aCol = lane >> 4;

    for (int chunk = 0; chunk < 16; ++chunk) {
        CP_WAIT1();
        __syncthreads();

        if (chunk + 2 < 16) issue_stage((chunk + 2) % 3, (chunk + 2) * 64);
        else CP_COMMIT();

        const int st = chunk % 3;
        const uint32_t aB = sbase + (uint32_t)(st * GSTAGE) * 2;
        const uint32_t bB = aB + 128 * GSTR * 2;

#pragma unroll
        for (int kk = 0; kk < 4; kk++) {
            uint32_t a[4][4];
#pragma unroll
            for (int mt = 0; mt < 4; mt++)
                LDSM4(a[mt][0], a[mt][1], a[mt][2], a[mt][3],
                      aB + (uint32_t)((wm * 64 + mt * 16 + lr8 + aRow * 8) * GSTR
                                      + kk * 16 + aCol * 8) * 2);
#pragma unroll
            for (int p = 0; p < 2; p++) {
                uint32_t b0, b1, b2, b3;
                LDSM4(b0, b1, b2, b3,
                      bB + (uint32_t)((wn * 32 + p * 16 + lr8 + aCol * 8) * GSTR
                                      + kk * 16 + aRow * 8) * 2);
#pragma unroll
                for (int mt = 0; mt < 4; mt++) {
                    mma_h(c[mt][2 * p],     a[mt][0], a[mt][1], a[mt][2], a[mt][3], b0, b1);
                    mma_h(c[mt][2 * p + 1], a[mt][0], a[mt][1], a[mt][2], a[mt][3], b2, b3);
                }
            }
        }
    }

    // epilogue: bias + scatter
    float2 bias2[4];
#pragma unroll
    for (int nt = 0; nt < 4; nt++) {
        const int col = colBase + wn * 32 + nt * 8 + tig * 2;
        bias2[nt] = *(const float2*)&bias[col];
    }

#pragma unroll
    for (int mt = 0; mt < 4; mt++)
#pragma unroll
        for (int nt = 0; nt < 4; nt++)
#pragma unroll
            for (int half_ = 0; half_ < 2; half_++) {
                const int row = rowBase + wm * 64 + mt * 16 + gid + half_ * 8;
                const int col = colBase + wn * 32 + nt * 8 + tig * 2;
                const float vx = c[mt][nt][half_ * 2 + 0] + bias2[nt].x;
                const float vy = c[mt][nt][half_ * 2 + 1] + bias2[nt].y;
                if (MODE == 2) {
                    float2 v; v.x = vx; v.y = vy;
                    *(float2*)(outp + (size_t)row * CC + col) = v;
                } else {
                    __half* dst;
                    if (MODE == 0) {
                        const int b_ = row >> 11, n = row & (NN - 1);
                        const int t3 = col >> 10, h = (col >> 6) & 15, d = col & 63;
                        const size_t bh = (size_t)b_ * HH + h;
                        if (t3 == 0)      dst = g_q + (bh * NN + n) * HD + d;
                        else if (t3 == 1) dst = g_k + (bh * SS + n) * HD + d;
                        else              dst = g_v + (bh * SS + n) * HD + d;
                    } else {
                        const int b_ = row >> 8, mm = row & (MM - 1);
                        const int t2 = col >> 10, h = (col >> 6) & 15, d = col & 63;
                        const size_t bh = (size_t)b_ * HH + h;
                        dst = (t2 == 0) ? g_k + (bh * SS + NN + mm) * HD + d
                                        : g_v + (bh * SS + NN + mm) * HD + d;
                    }
                    __half2 hv = __floats2half2_rn(vx, vy);
                    *(__half2*)dst = hv;
                }
            }
}

// ---------------------------------------------------------------------------
// RMSNorm over head_dim=64 (fp16 in/out). q rows get x0.125 folded in.
// ---------------------------------------------------------------------------
#define QROWS (BB * HH * NN)
#define KROWS (BB * HH * SS)

__global__ __launch_bounds__(256) void rmsnorm_kernel(const float* __restrict__ wq,
                                                      const float* __restrict__ wk)
{
    const int row  = blockIdx.x * 8 + (threadIdx.x >> 5);
    const int lane = threadIdx.x & 31;
    const bool isq = row < QROWS;
    __half2* p = isq ? (__half2*)g_q + (size_t)row * 32
                     : (__half2*)g_k + (size_t)(row - QROWS) * 32;
    const float* w = isq ? wq : wk;
    const float2 f = __half22float2(p[lane]);
    float ss = f.x * f.x + f.y * f.y;
#pragma unroll
    for (int o = 16; o; o >>= 1) ss += __shfl_xor_sync(0xffffffffu, ss, o);
    float inv = rsqrtf(ss * (1.0f / 64.0f) + 1e-6f);
    if (isq) inv *= 0.125f;
    p[lane] = __floats2half2_rn(f.x * inv * w[2 * lane], f.y * inv * w[2 * lane + 1]);
}

// ---------------------------------------------------------------------------
// fp16 flash attention; Q and P live in registers (FA2 fragment reuse).
// CTA: 128 queries x (b,h); 8 warps x 16 q rows; S-chunks of 64 (36 iters).
// smem: 3 stages x (K[64][72] + V[64][72]) halves = 55296 B.
// ---------------------------------------------------------------------------
#define ASTR 72
#define KVSTG (2 * 64 * ASTR)              // halves per stage (K+V)
#define ATTN_SMEM (3 * KVSTG * 2)          // 55296 bytes

__global__ __launch_bounds__(256, 2) void attn_mma()
{
    extern __shared__ __half sh[];
    const uint32_t sbase = smem_u32(sh);

    const int tid  = threadIdx.x;
    const int lane = tid & 31;
    const int wid  = tid >> 5;
    const int gid  = lane >> 2;
    const int tig  = lane & 3;
    const int lr8  = lane & 7;
    const int aRow = (lane >> 3) & 1;
    const int aCol = lane >> 4;

    const int qb = blockIdx.x * 128;
    const int h  = blockIdx.y;
    const int b  = blockIdx.z;
    const size_t bh = (size_t)b * HH + h;

    const __half* qg = g_q + (bh * NN + qb) * HD;
    const __half* kg = g_k + bh * SS * HD;
    const __half* vg = g_v + bh * SS * HD;

    const int kv_row = tid >> 2;
    const int kv_sg  = tid & 3;
    auto issue_stage = [&](int stage, int sc) {
        const uint32_t kOff = sbase + (uint32_t)(stage * KVSTG) * 2;
        const uint32_t vOff = kOff + 64 * ASTR * 2;
#pragma unroll
        for (int i = 0; i < 2; i++) {
            const int seg = kv_sg * 2 + i;
            const uint32_t d = (uint32_t)(kv_row * ASTR + seg * 8) * 2;
            CP16(kOff + d, kg + (size_t)(sc + kv_row) * HD + seg * 8);
            CP16(vOff + d, vg + (size_t)(sc + kv_row) * HD + seg * 8);
        }
        CP_COMMIT();
    };

    issue_stage(0, 0);
    issue_stage(1, 64);

    // stage Q through the (not yet used) stage-2 region, pull into fragments
    const int wrow = wid * 16;
    uint32_t qf[4][4];
    {
        __half* qsm = sh + 2 * KVSTG;      // 128 rows x ASTR (spans K+V of stage 2)
#pragma unroll
        for (int i = 0; i < 4; i++) {
            const int u = tid + 256 * i;
            const int row = u >> 3, seg = u & 7;
            *(uint4*)&qsm[row * ASTR + seg * 8] =
                *(const uint4*)&qg[(size_t)row * HD + seg * 8];
        }
        __syncthreads();
        const uint32_t qB = sbase + (uint32_t)(2 * KVSTG) * 2;
#pragma unroll
        for (int kk = 0; kk < 4; kk++)
            LDSM4(qf[kk][0], qf[kk][1], qf[kk][2], qf[kk][3],
                  qB + (uint32_t)((wrow + lr8 + aRow * 8) * ASTR
                                  + kk * 16 + aCol * 8) * 2);
        __syncthreads();   // everyone has Q; stage-2 region reusable
    }

    float oacc[8][4];
#pragma unroll
    for (int nt = 0; nt < 8; nt++)
#pragma unroll
        for (int q = 0; q < 4; q++) oacc[nt][q] = 0.f;
    float l0 = 0.f, l1 = 0.f;

    for (int c = 0; c < 36; ++c) {
        CP_WAIT1();
        __syncthreads();

        if (c + 2 < 36) issue_stage((c + 2) % 3, (c + 2) * 64);
        else CP_COMMIT();

        const int st = c % 3;
        const uint32_t ksB = sbase + (uint32_t)(st * KVSTG) * 2;
        const uint32_t vsB = ksB + 64 * ASTR * 2;

        // ---- S = Q @ K^T (q pre-scaled; |logit| <= 8) ----
        float s[8][4];
#pragma unroll
        for (int nt = 0; nt < 8; nt++)
#pragma unroll
            for (int q = 0; q < 4; q++) s[nt][q] = 0.f;

#pragma unroll
        for (int kk = 0; kk < 4; kk++) {
#pragma unroll
            for (int p = 0; p < 4; p++) {
                uint32_t b0, b1, b2, b3;
                LDSM4(b0, b1, b2, b3,
                      ksB + (uint32_t)((p * 16 + lr8 + aCol * 8) * ASTR
                                       + kk * 16 + aRow * 8) * 2);
                mma_h(s[2 * p],     qf[kk][0], qf[kk][1], qf[kk][2], qf[kk][3], b0, b1);
                mma_h(s[2 * p + 1], qf[kk][0], qf[kk][1], qf[kk][2], qf[kk][3], b2, b3);
            }
        }

        // ---- fixed-shift softmax in registers ----
        uint32_t hlo[8], hhi[8];
        float rs0 = 0.f, rs1 = 0.f;
#pragma unroll
        for (int nt = 0; nt < 8; nt++) {
            const float p00 = __expf(s[nt][0] - 8.0f);
            const float p01 = __expf(s[nt][1] - 8.0f);
            const float p10 = __expf(s[nt][2] - 8.0f);
            const float p11 = __expf(s[nt][3] - 8.0f);
            rs0 += p00 + p01;
            rs1 += p10 + p11;
            hlo[nt] = pack_h2(p00, p01);
            hhi[nt] = pack_h2(p10, p11);
        }
        l0 += rs0;
        l1 += rs1;

        // ---- O += P @ V, P straight from fragments ----
#pragma unroll
        for (int kk = 0; kk < 4; kk++) {
            const uint32_t a0 = hlo[2 * kk],     a1 = hhi[2 * kk];
            const uint32_t a2 = hlo[2 * kk + 1], a3 = hhi[2 * kk + 1];
#pragma unroll
            for (int p = 0; p < 4; p++) {
                uint32_t b0, b1, b2, b3;
                LDSM4T(b0, b1, b2, b3,
                       vsB + (uint32_t)((kk * 16 + lr8 + aRow * 8) * ASTR
                                        + p * 16 + aCol * 8) * 2);
                mma_h(oacc[2 * p],     a0, a1, a2, a3, b0, b1);
                mma_h(oacc[2 * p + 1], a0, a1, a2, a3, b2, b3);
            }
        }
    }

    // ---- epilogue: quad-reduce l, normalize, write fp16 ----
    l0 += __shfl_xor_sync(0xffffffffu, l0, 1);
    l0 += __shfl_xor_sync(0xffffffffu, l0, 2);
    l1 += __shfl_xor_sync(0xffffffffu, l1, 1);
    l1 += __shfl_xor_sync(0xffffffffu, l1, 2);
    const float inv0 = 1.0f / l0;
    const float inv1 = 1.0f / l1;
    const int n0 = qb + wrow + gid;
    const int n1 = n0 + 8;
#pragma unroll
    for (int nt = 0; nt < 8; nt++) {
        const int d = h * HD + nt * 8 + tig * 2;
        *(__half2*)&g_ao[((size_t)b * NN + n0) * CC + d] =
            __floats2half2_rn(oacc[nt][0] * inv0, oacc[nt][1] * inv0);
        *(__half2*)&g_ao[((size_t)b * NN + n1) * CC + d] =
            __floats2half2_rn(oacc[nt][2] * inv1, oacc[nt][3] * inv1);
    }
}

// ---------------------------------------------------------------------------
extern "C" void kernel_launch(void* const* d_in, const int* in_sizes, int n_in,
                              void* d_out, int out_size)
{
    const float* x      = (const float*)d_in[0];
    const float* y      = (const float*)d_in[1];
    const float* qkv_w  = (const float*)d_in[2];
    const float* qkv_b  = (const float*)d_in[3];
    const float* kv_w   = (const float*)d_in[4];
    const float* kv_b   = (const float*)d_in[5];
    const float* qn_w   = (const float*)d_in[6];
    const float* kn_w   = (const float*)d_in[7];
    const float* proj_w = (const float*)d_in[8];
    const float* proj_b = (const float*)d_in[9];
    float* out = (float*)d_out;

    (void)in_sizes; (void)n_in; (void)out_size;

    cudaFuncSetAttribute(gemm_mma<0>, cudaFuncAttributeMaxDynamicSharedMemorySize, GEMM_SMEM);
    cudaFuncSetAttribute(gemm_mma<1>, cudaFuncAttributeMaxDynamicSharedMemorySize, GEMM_SMEM);
    cudaFuncSetAttribute(gemm_mma<2>, cudaFuncAttributeMaxDynamicSharedMemorySize, GEMM_SMEM);
    cudaFuncSetAttribute(attn_mma, cudaFuncAttributeMaxDynamicSharedMemorySize, ATTN_SMEM);

    // single merged fp32->fp16 conversion pass (segment sizes fixed!)
    cvt_all<<<CVT_BLOCKS, 256>>>(x, y, qkv_w, kv_w, proj_w);

    // QKV projection (image)
    gemm_mma<0><<<dim3(3 * CC / 128, BB * NN / 128), 256, GEMM_SMEM>>>(qkv_b, nullptr);
    // KV projection (text)
    gemm_mma<1><<<dim3(2 * CC / 128, BB * MM / 128), 256, GEMM_SMEM>>>(kv_b, nullptr);
    // RMSNorm q (+0.125) and k
    rmsnorm_kernel<<<(QROWS + KROWS) / 8, 256>>>(qn_w, kn_w);
    // Attention (register-resident Q/P)
    attn_mma<<<dim3(NN / 128, HH, BB), 256, ATTN_SMEM>>>();
    // Output projection -> d_out
    gemm_mma<2><<<dim3(CC / 128, BB * NN / 128), 256, GEMM_SMEM>>>(proj_b, out);
}

// round 9
// speedup vs baseline: 6.0231x; 1.0497x over previous
#include <cuda_runtime.h>
#include <cuda_fp16.h>
#include <cstdint>
#include <cstddef>

// Problem constants
#define BB   2
#define NN   2048
#define MM   256
#define CC   1024
#define HH   16
#define HD   64
#define SS   2304   // NN + MM

// q pre-scale: hd^-0.5 * log2(e), so QK logits are in log2 domain
#define QSCALE 0.18033688011112042f
// softmax shift: 8 * log2(e)
#define CSH    11.541560327111707f
#define HONES  0x3C003C00u

// Scratch (device globals; fp16 activations)
__device__ __half g_q [(size_t)BB * HH * NN * HD];   // [B,H,N,hd] (rms-normed, xQSCALE)
__device__ __half g_k [(size_t)BB * HH * SS * HD];   // [B,H,S,hd] (rms-normed)
__device__ __half g_v [(size_t)BB * HH * SS * HD];   // [B,H,S,hd]
__device__ __half g_ao[(size_t)BB * NN * CC];        // [B,N,C] attn out
// fp16-preconverted inputs
__device__ __half g_xh  [(size_t)BB * NN * CC];
__device__ __half g_yh  [(size_t)BB * MM * CC];
__device__ __half g_wqkv[(size_t)3 * CC * CC];
__device__ __half g_wkv [(size_t)2 * CC * CC];
__device__ __half g_wp  [(size_t)CC * CC];

// ---------------------------------------------------------------------------
// helpers
// ---------------------------------------------------------------------------
__device__ __forceinline__ uint32_t smem_u32(const void* p) {
    uint32_t a;
    asm("{ .reg .u64 t; cvta.to.shared.u64 t, %1; cvt.u32.u64 %0, t; }"
        : "=r"(a) : "l"(p));
    return a;
}

// m16n8k16 fp16 mma, fp32 accumulate
__device__ __forceinline__ void mma_h(float* c, uint32_t a0, uint32_t a1,
                                      uint32_t a2, uint32_t a3,
                                      uint32_t b0, uint32_t b1) {
    asm volatile(
        "mma.sync.aligned.m16n8k16.row.col.f32.f16.f16.f32 "
        "{%0,%1,%2,%3}, {%4,%5,%6,%7}, {%8,%9}, {%0,%1,%2,%3};"
        : "+f"(c[0]), "+f"(c[1]), "+f"(c[2]), "+f"(c[3])
        : "r"(a0), "r"(a1), "r"(a2), "r"(a3), "r"(b0), "r"(b1));
}

__device__ __forceinline__ uint32_t pack_h2(float x, float y) {
    __half2 h = __floats2half2_rn(x, y);
    return *reinterpret_cast<uint32_t*>(&h);
}

__device__ __forceinline__ uint32_t ex2_h2(uint32_t a) {
    uint32_t r;
    asm("ex2.approx.f16x2 %0, %1;" : "=r"(r) : "r"(a));
    return r;
}

#define LDSM4(r0, r1, r2, r3, addr)                                           \
    asm volatile("ldmatrix.sync.aligned.m8n8.x4.shared.b16 {%0,%1,%2,%3}, [%4];" \
                 : "=r"(r0), "=r"(r1), "=r"(r2), "=r"(r3) : "r"(addr))
#define LDSM4T(r0, r1, r2, r3, addr)                                          \
    asm volatile("ldmatrix.sync.aligned.m8n8.x4.trans.shared.b16 {%0,%1,%2,%3}, [%4];" \
                 : "=r"(r0), "=r"(r1), "=r"(r2), "=r"(r3) : "r"(addr))

#define CP16(smem_addr, gptr)                                                 \
    asm volatile("cp.async.cg.shared.global [%0], [%1], 16;"                  \
                 :: "r"(smem_addr), "l"(gptr) : "memory")
#define CP_COMMIT() asm volatile("cp.async.commit_group;" ::: "memory")
#define CP_WAIT1()  asm volatile("cp.async.wait_group 1;"  ::: "memory")

// ---------------------------------------------------------------------------
// merged fp32 -> fp16 pre-convert (x | y | qkv_w | kv_w | proj_w), one launch
// ---------------------------------------------------------------------------
#define XB  ((BB * NN * CC) / 1024)        // 4096
#define YB  ((BB * MM * CC) / 1024)        // 512
#define W3B ((3 * CC * CC) / 1024)         // 3072
#define W2B ((2 * CC * CC) / 1024)         // 2048
#define W1B ((CC * CC) / 1024)             // 1024
#define CVT_BLOCKS (XB + YB + W3B + W2B + W1B)

__global__ __launch_bounds__(256) void cvt_all(const float* __restrict__ x,
                                               const float* __restrict__ y,
                                               const float* __restrict__ wqkv,
                                               const float* __restrict__ wkv,
                                               const float* __restrict__ wp)
{
    int blk = blockIdx.x;
    const float* src;
    __half* dst;
    if (blk < XB)                    { src = x;    dst = g_xh; }
    else if ((blk -= XB) < YB)       { src = y;    dst = g_yh; }
    else if ((blk -= YB) < W3B)      { src = wqkv; dst = g_wqkv; }
    else if ((blk -= W3B) < W2B)     { src = wkv;  dst = g_wkv; }
    else                             { blk -= W2B; src = wp; dst = g_wp; }
    const size_t i = ((size_t)blk * 256 + threadIdx.x) * 4;
    float4 v = *(const float4*)(src + i);
    uint2 u;
    u.x = pack_h2(v.x, v.y);
    u.y = pack_h2(v.z, v.w);
    *(uint2*)(dst + i) = u;
}

// ---------------------------------------------------------------------------
// fp16 NT GEMM: out[r,o] = sum_c A[r,c]*W[o,c] + bias[o]
// 128x128 tile, K-chunk 64, 3-stage cp.async, ldmatrix, m16n8k16 mma.
// ---------------------------------------------------------------------------
#define GSTR 72
#define GSTAGE (2 * 128 * GSTR)            // halves per stage
#define GEMM_SMEM (3 * GSTAGE * 2)         // 110592 bytes

template <int MODE>
__global__ __launch_bounds__(256, 2) void gemm_mma(const float* __restrict__ bias,
                                                   float* __restrict__ outp)
{
    extern __shared__ __half smh[];
    const uint32_t sbase = smem_u32(smh);

    const int tid  = threadIdx.x;
    const int lane = tid & 31;
    const int wid  = tid >> 5;
    const int wm   = wid >> 2;
    const int wn   = wid & 3;
    const int gid  = lane >> 2;
    const int tig  = lane & 3;

    const int rowBase = blockIdx.y * 128;
    const int colBase = blockIdx.x * 128;

    const __half* Aptr = (MODE == 0) ? g_xh : (MODE == 1) ? g_yh : g_ao;
    const __half* Wptr = (MODE == 0) ? g_wqkv : (MODE == 1) ? g_wkv : g_wp;

    const int u_row = tid >> 1;          // 0..127
    const int u_s4  = (tid & 1) * 4;

    auto issue_stage = [&](int stage, int k0) {
        const uint32_t aOff = sbase + (uint32_t)(stage * GSTAGE) * 2;
        const uint32_t bOff = aOff + 128 * GSTR * 2;
#pragma unroll
        for (int i = 0; i < 4; i++) {
            const int seg = u_s4 + i;
            const uint32_t d = (uint32_t)(u_row * GSTR + seg * 8) * 2;
            CP16(aOff + d, Aptr + (size_t)(rowBase + u_row) * CC + k0 + seg * 8);
            CP16(bOff + d, Wptr + (size_t)(colBase + u_row) * CC + k0 + seg * 8);
        }
        CP_COMMIT();
    };

    float c[4][4][4];
#pragma unroll
    for (int mt = 0; mt < 4; mt++)
#pragma unroll
        for (int nt = 0; nt < 4; nt++)
#pragma unroll
            for (int q = 0; q < 4; q++) c[mt][nt][q] = 0.f;

    issue_stage(0, 0);
    issue_stage(1, 64);

    const int lr8  = lane & 7;
    const int aRow = (lane >> 3) & 1;
    const int aCol = lane >> 4;

    for (int chunk = 0; chunk < 16; ++chunk) {
        CP_WAIT1();
        __syncthreads();

        if (chunk + 2 < 16) issue_stage((chunk + 2) % 3, (chunk + 2) * 64);
        else CP_COMMIT();

        const int st = chunk % 3;
        const uint32_t aB = sbase + (uint32_t)(st * GSTAGE) * 2;
        const uint32_t bB = aB + 128 * GSTR * 2;

#pragma unroll
        for (int kk = 0; kk < 4; kk++) {
            uint32_t a[4][4];
#pragma unroll
            for (int mt = 0; mt < 4; mt++)
                LDSM4(a[mt][0], a[mt][1], a[mt][2], a[mt][3],
                      aB + (uint32_t)((wm * 64 + mt * 16 + lr8 + aRow * 8) * GSTR
                                      + kk * 16 + aCol * 8) * 2);
#pragma unroll
            for (int p = 0; p < 2; p++) {
                uint32_t b0, b1, b2, b3;
                LDSM4(b0, b1, b2, b3,
                      bB + (uint32_t)((wn * 32 + p * 16 + lr8 + aCol * 8) * GSTR
                                      + kk * 16 + aRow * 8) * 2);
#pragma unroll
                for (int mt = 0; mt < 4; mt++) {
                    mma_h(c[mt][2 * p],     a[mt][0], a[mt][1], a[mt][2], a[mt][3], b0, b1);
                    mma_h(c[mt][2 * p + 1], a[mt][0], a[mt][1], a[mt][2], a[mt][3], b2, b3);
                }
            }
        }
    }

    // epilogue: bias + scatter
    float2 bias2[4];
#pragma unroll
    for (int nt = 0; nt < 4; nt++) {
        const int col = colBase + wn * 32 + nt * 8 + tig * 2;
        bias2[nt] = *(const float2*)&bias[col];
    }

#pragma unroll
    for (int mt = 0; mt < 4; mt++)
#pragma unroll
        for (int nt = 0; nt < 4; nt++)
#pragma unroll
            for (int half_ = 0; half_ < 2; half_++) {
                const int row = rowBase + wm * 64 + mt * 16 + gid + half_ * 8;
                const int col = colBase + wn * 32 + nt * 8 + tig * 2;
                const float vx = c[mt][nt][half_ * 2 + 0] + bias2[nt].x;
                const float vy = c[mt][nt][half_ * 2 + 1] + bias2[nt].y;
                if (MODE == 2) {
                    float2 v; v.x = vx; v.y = vy;
                    *(float2*)(outp + (size_t)row * CC + col) = v;
                } else {
                    __half* dst;
                    if (MODE == 0) {
                        const int b_ = row >> 11, n = row & (NN - 1);
                        const int t3 = col >> 10, h = (col >> 6) & 15, d = col & 63;
                        const size_t bh = (size_t)b_ * HH + h;
                        if (t3 == 0)      dst = g_q + (bh * NN + n) * HD + d;
                        else if (t3 == 1) dst = g_k + (bh * SS + n) * HD + d;
                        else              dst = g_v + (bh * SS + n) * HD + d;
                    } else {
                        const int b_ = row >> 8, mm = row & (MM - 1);
                        const int t2 = col >> 10, h = (col >> 6) & 15, d = col & 63;
                        const size_t bh = (size_t)b_ * HH + h;
                        dst = (t2 == 0) ? g_k + (bh * SS + NN + mm) * HD + d
                                        : g_v + (bh * SS + NN + mm) * HD + d;
                    }
                    __half2 hv = __floats2half2_rn(vx, vy);
                    *(__half2*)dst = hv;
                }
            }
}

// ---------------------------------------------------------------------------
// RMSNorm over head_dim=64 (fp16 in/out). 8 threads/row, uint4 loads.
// q rows get QSCALE (hd^-0.5 * log2e) folded in.
// ---------------------------------------------------------------------------
#define QROWS (BB * HH * NN)
#define KROWS (BB * HH * SS)

__global__ __launch_bounds__(256) void rmsnorm_kernel(const float* __restrict__ wq,
                                                      const float* __restrict__ wk)
{
    const int row = blockIdx.x * 32 + (threadIdx.x >> 3);
    const int sub = threadIdx.x & 7;
    const bool isq = row < QROWS;
    __half* p = isq ? g_q + (size_t)row * HD
                    : g_k + (size_t)(row - QROWS) * HD;
    const float* w = isq ? wq : wk;

    uint4 u = *(uint4*)(p + sub * 8);
    __half2* h = (__half2*)&u;
    float2 f[4];
    float ss = 0.f;
#pragma unroll
    for (int i = 0; i < 4; i++) {
        f[i] = __half22float2(h[i]);
        ss += f[i].x * f[i].x + f[i].y * f[i].y;
    }
    ss += __shfl_xor_sync(0xffffffffu, ss, 1);
    ss += __shfl_xor_sync(0xffffffffu, ss, 2);
    ss += __shfl_xor_sync(0xffffffffu, ss, 4);
    float inv = rsqrtf(ss * (1.0f / 64.0f) + 1e-6f);
    if (isq) inv *= QSCALE;

    const float4 w0 = *(const float4*)(w + sub * 8);
    const float4 w1 = *(const float4*)(w + sub * 8 + 4);
    h[0] = __floats2half2_rn(f[0].x * inv * w0.x, f[0].y * inv * w0.y);
    h[1] = __floats2half2_rn(f[1].x * inv * w0.z, f[1].y * inv * w0.w);
    h[2] = __floats2half2_rn(f[2].x * inv * w1.x, f[2].y * inv * w1.y);
    h[3] = __floats2half2_rn(f[3].x * inv * w1.z, f[3].y * inv * w1.w);
    *(uint4*)(p + sub * 8) = u;
}

// ---------------------------------------------------------------------------
// fp16 flash attention; Q and P in registers; ex2.f16x2 softmax; l via
// ones-column mma. CTA: 128 queries x (b,h); 8 warps; S-chunks of 64.
// smem: 3 stages x (K[64][72] + V[64][72]) halves = 55296 B.
// ---------------------------------------------------------------------------
#define ASTR 72
#define KVSTG (2 * 64 * ASTR)              // halves per stage (K+V)
#define ATTN_SMEM (3 * KVSTG * 2)          // 55296 bytes

__global__ __launch_bounds__(256, 2) void attn_mma()
{
    extern __shared__ __half sh[];
    const uint32_t sbase = smem_u32(sh);

    const int tid  = threadIdx.x;
    const int lane = tid & 31;
    const int wid  = tid >> 5;
    const int gid  = lane >> 2;
    const int tig  = lane & 3;
    const int lr8  = lane & 7;
    const int aRow = (lane >> 3) & 1;
    const int aCol = lane >> 4;

    const int qb = blockIdx.x * 128;
    const int h  = blockIdx.y;
    const int b  = blockIdx.z;
    const size_t bh = (size_t)b * HH + h;

    const __half* qg = g_q + (bh * NN + qb) * HD;
    const __half* kg = g_k + bh * SS * HD;
    const __half* vg = g_v + bh * SS * HD;

    const int kv_row = tid >> 2;
    const int kv_sg  = tid & 3;
    auto issue_stage = [&](int stage, int sc) {
        const uint32_t kOff = sbase + (uint32_t)(stage * KVSTG) * 2;
        const uint32_t vOff = kOff + 64 * ASTR * 2;
#pragma unroll
        for (int i = 0; i < 2; i++) {
            const int seg = kv_sg * 2 + i;
            const uint32_t d = (uint32_t)(kv_row * ASTR + seg * 8) * 2;
            CP16(kOff + d, kg + (size_t)(sc + kv_row) * HD + seg * 8);
            CP16(vOff + d, vg + (size_t)(sc + kv_row) * HD + seg * 8);
        }
        CP_COMMIT();
    };

    issue_stage(0, 0);
    issue_stage(1, 64);

    // stage Q through the stage-2 region, pull into fragments
    const int wrow = wid * 16;
    uint32_t qf[4][4];
    {
        __half* qsm = sh + 2 * KVSTG;
#pragma unroll
        for (int i = 0; i < 4; i++) {
            const int u = tid + 256 * i;
            const int row = u >> 3, seg = u & 7;
            *(uint4*)&qsm[row * ASTR + seg * 8] =
                *(const uint4*)&qg[(size_t)row * HD + seg * 8];
        }
        __syncthreads();
        const uint32_t qB = sbase + (uint32_t)(2 * KVSTG) * 2;
#pragma unroll
        for (int kk = 0; kk < 4; kk++)
            LDSM4(qf[kk][0], qf[kk][1], qf[kk][2], qf[kk][3],
                  qB + (uint32_t)((wrow + lr8 + aRow * 8) * ASTR
                                  + kk * 16 + aCol * 8) * 2);
        __syncthreads();
    }

    float oacc[8][4];
#pragma unroll
    for (int nt = 0; nt < 8; nt++)
#pragma unroll
        for (int q = 0; q < 4; q++) oacc[nt][q] = 0.f;
    float lacc[4] = {0.f, 0.f, 0.f, 0.f};

    for (int c = 0; c < 36; ++c) {
        CP_WAIT1();
        __syncthreads();

        if (c + 2 < 36) issue_stage((c + 2) % 3, (c + 2) * 64);
        else CP_COMMIT();

        const int st = c % 3;
        const uint32_t ksB = sbase + (uint32_t)(st * KVSTG) * 2;
        const uint32_t vsB = ksB + 64 * ASTR * 2;

        // ---- S = Q @ K^T (log2-domain logits, |S| <= CSH) ----
        float s[8][4];
#pragma unroll
        for (int nt = 0; nt < 8; nt++)
#pragma unroll
            for (int q = 0; q < 4; q++) s[nt][q] = 0.f;

#pragma unroll
        for (int kk = 0; kk < 4; kk++) {
#pragma unroll
            for (int p = 0; p < 4; p++) {
                uint32_t b0, b1, b2, b3;
                LDSM4(b0, b1, b2, b3,
                      ksB + (uint32_t)((p * 16 + lr8 + aCol * 8) * ASTR
                                       + kk * 16 + aRow * 8) * 2);
                mma_h(s[2 * p],     qf[kk][0], qf[kk][1], qf[kk][2], qf[kk][3], b0, b1);
                mma_h(s[2 * p + 1], qf[kk][0], qf[kk][1], qf[kk][2], qf[kk][3], b2, b3);
            }
        }

        // ---- softmax: p = 2^(S - CSH) via f16x2 ex2 ----
        uint32_t hlo[8], hhi[8];
#pragma unroll
        for (int nt = 0; nt < 8; nt++) {
            hlo[nt] = ex2_h2(pack_h2(s[nt][0] - CSH, s[nt][1] - CSH));
            hhi[nt] = ex2_h2(pack_h2(s[nt][2] - CSH, s[nt][3] - CSH));
        }

        // ---- l via ones-column mma; O += P @ V ----
#pragma unroll
        for (int kk = 0; kk < 4; kk++) {
            const uint32_t a0 = hlo[2 * kk],     a1 = hhi[2 * kk];
            const uint32_t a2 = hlo[2 * kk + 1], a3 = hhi[2 * kk + 1];
            mma_h(lacc, a0, a1, a2, a3, HONES, HONES);
#pragma unroll
            for (int p = 0; p < 4; p++) {
                uint32_t b0, b1, b2, b3;
                LDSM4T(b0, b1, b2, b3,
                       vsB + (uint32_t)((kk * 16 + lr8 + aRow * 8) * ASTR
                                        + p * 16 + aCol * 8) * 2);
                mma_h(oacc[2 * p],     a0, a1, a2, a3, b0, b1);
                mma_h(oacc[2 * p + 1], a0, a1, a2, a3, b2, b3);
            }
        }
    }

    // ---- epilogue: normalize (l already per-thread), write fp16 ----
    const float inv0 = 1.0f / lacc[0];
    const float inv1 = 1.0f / lacc[2];
    const int n0 = qb + wrow + gid;
    const int n1 = n0 + 8;
#pragma unroll
    for (int nt = 0; nt < 8; nt++) {
        const int d = h * HD + nt * 8 + tig * 2;
        *(__half2*)&g_ao[((size_t)b * NN + n0) * CC + d] =
            __floats2half2_rn(oacc[nt][0] * inv0, oacc[nt][1] * inv0);
        *(__half2*)&g_ao[((size_t)b * NN + n1) * CC + d] =
            __floats2half2_rn(oacc[nt][2] * inv1, oacc[nt][3] * inv1);
    }
}

// ---------------------------------------------------------------------------
extern "C" void kernel_launch(void* const* d_in, const int* in_sizes, int n_in,
                              void* d_out, int out_size)
{
    const float* x      = (const float*)d_in[0];
    const float* y      = (const float*)d_in[1];
    const float* qkv_w  = (const float*)d_in[2];
    const float* qkv_b  = (const float*)d_in[3];
    const float* kv_w   = (const float*)d_in[4];
    const float* kv_b   = (const float*)d_in[5];
    const float* qn_w   = (const float*)d_in[6];
    const float* kn_w   = (const float*)d_in[7];
    const float* proj_w = (const float*)d_in[8];
    const float* proj_b = (const float*)d_in[9];
    float* out = (float*)d_out;

    (void)in_sizes; (void)n_in; (void)out_size;

    cudaFuncSetAttribute(gemm_mma<0>, cudaFuncAttributeMaxDynamicSharedMemorySize, GEMM_SMEM);
    cudaFuncSetAttribute(gemm_mma<1>, cudaFuncAttributeMaxDynamicSharedMemorySize, GEMM_SMEM);
    cudaFuncSetAttribute(gemm_mma<2>, cudaFuncAttributeMaxDynamicSharedMemorySize, GEMM_SMEM);
    cudaFuncSetAttribute(attn_mma, cudaFuncAttributeMaxDynamicSharedMemorySize, ATTN_SMEM);

    // single merged fp32->fp16 conversion pass
    cvt_all<<<CVT_BLOCKS, 256>>>(x, y, qkv_w, kv_w, proj_w);

    // QKV projection (image)
    gemm_mma<0><<<dim3(3 * CC / 128, BB * NN / 128), 256, GEMM_SMEM>>>(qkv_b, nullptr);
    // KV projection (text)
    gemm_mma<1><<<dim3(2 * CC / 128, BB * MM / 128), 256, GEMM_SMEM>>>(kv_b, nullptr);
    // RMSNorm q (xQSCALE) and k
    rmsnorm_kernel<<<(QROWS + KROWS) / 32, 256>>>(qn_w, kn_w);
    // Attention
    attn_mma<<<dim3(NN / 128, HH, BB), 256, ATTN_SMEM>>>();
    // Output projection -> d_out
    gemm_mma<2><<<dim3(CC / 128, BB * NN / 128), 256, GEMM_SMEM>>>(proj_b, out);
}

// round 10
// speedup vs baseline: 6.5881x; 1.0938x over previous
#include <cuda_runtime.h>
#include <cuda_fp16.h>
#include <cstdint>
#include <cstddef>

// Problem constants
#define BB   2
#define NN   2048
#define MM   256
#define CC   1024
#define HH   16
#define HD   64
#define SS   2304   // NN + MM

// q pre-scale: hd^-0.5 * log2(e) -> QK logits in log2 domain
#define QSCALE 0.18033688011112042f
// softmax shift: 8 * log2(e)
#define CSH    11.541560327111707f
#define HONES  0x3C003C00u

// Scratch (device globals; fp16 activations)
__device__ __half g_q [(size_t)BB * HH * NN * HD];   // [B,H,N,hd] (rms-normed, xQSCALE)
__device__ __half g_k [(size_t)BB * HH * SS * HD];   // [B,H,S,hd] (rms-normed)
__device__ __half g_v [(size_t)BB * HH * SS * HD];   // [B,H,S,hd]
__device__ __half g_ao[(size_t)BB * NN * CC];        // [B,N,C] attn out
// fp16-preconverted inputs
__device__ __half g_xh  [(size_t)BB * NN * CC];
__device__ __half g_yh  [(size_t)BB * MM * CC];
__device__ __half g_wqkv[(size_t)3 * CC * CC];
__device__ __half g_wkv [(size_t)2 * CC * CC];
__device__ __half g_wp  [(size_t)CC * CC];

// ---------------------------------------------------------------------------
// helpers
// ---------------------------------------------------------------------------
__device__ __forceinline__ uint32_t smem_u32(const void* p) {
    uint32_t a;
    asm("{ .reg .u64 t; cvta.to.shared.u64 t, %1; cvt.u32.u64 %0, t; }"
        : "=r"(a) : "l"(p));
    return a;
}

// m16n8k16 fp16 mma, fp32 accumulate
__device__ __forceinline__ void mma_h(float* c, uint32_t a0, uint32_t a1,
                                      uint32_t a2, uint32_t a3,
                                      uint32_t b0, uint32_t b1) {
    asm volatile(
        "mma.sync.aligned.m16n8k16.row.col.f32.f16.f16.f32 "
        "{%0,%1,%2,%3}, {%4,%5,%6,%7}, {%8,%9}, {%0,%1,%2,%3};"
        : "+f"(c[0]), "+f"(c[1]), "+f"(c[2]), "+f"(c[3])
        : "r"(a0), "r"(a1), "r"(a2), "r"(a3), "r"(b0), "r"(b1));
}

__device__ __forceinline__ uint32_t pack_h2(float x, float y) {
    __half2 h = __floats2half2_rn(x, y);
    return *reinterpret_cast<uint32_t*>(&h);
}

__device__ __forceinline__ float ex2f(float x) {
    float r;
    asm("ex2.approx.f32 %0, %1;" : "=f"(r) : "f"(x));
    return r;
}

#define LDSM4(r0, r1, r2, r3, addr)                                           \
    asm volatile("ldmatrix.sync.aligned.m8n8.x4.shared.b16 {%0,%1,%2,%3}, [%4];" \
                 : "=r"(r0), "=r"(r1), "=r"(r2), "=r"(r3) : "r"(addr))
#define LDSM4T(r0, r1, r2, r3, addr)                                          \
    asm volatile("ldmatrix.sync.aligned.m8n8.x4.trans.shared.b16 {%0,%1,%2,%3}, [%4];" \
                 : "=r"(r0), "=r"(r1), "=r"(r2), "=r"(r3) : "r"(addr))

#define CP16(smem_addr, gptr)                                                 \
    asm volatile("cp.async.cg.shared.global [%0], [%1], 16;"                  \
                 :: "r"(smem_addr), "l"(gptr) : "memory")
#define CP_COMMIT() asm volatile("cp.async.commit_group;" ::: "memory")
#define CP_WAIT1()  asm volatile("cp.async.wait_group 1;"  ::: "memory")

// ---------------------------------------------------------------------------
// merged fp32 -> fp16 pre-convert (x | y | qkv_w | kv_w | proj_w), one launch
// ---------------------------------------------------------------------------
#define XB  ((BB * NN * CC) / 1024)        // 4096
#define YB  ((BB * MM * CC) / 1024)        // 512
#define W3B ((3 * CC * CC) / 1024)         // 3072
#define W2B ((2 * CC * CC) / 1024)         // 2048
#define W1B ((CC * CC) / 1024)             // 1024
#define CVT_BLOCKS (XB + YB + W3B + W2B + W1B)

__global__ __launch_bounds__(256) void cvt_all(const float* __restrict__ x,
                                               const float* __restrict__ y,
                                               const float* __restrict__ wqkv,
                                               const float* __restrict__ wkv,
                                               const float* __restrict__ wp)
{
    int blk = blockIdx.x;
    const float* src;
    __half* dst;
    if (blk < XB)                    { src = x;    dst = g_xh; }
    else if ((blk -= XB) < YB)       { src = y;    dst = g_yh; }
    else if ((blk -= YB) < W3B)      { src = wqkv; dst = g_wqkv; }
    else if ((blk -= W3B) < W2B)     { src = wkv;  dst = g_wkv; }
    else                             { blk -= W2B; src = wp; dst = g_wp; }
    const size_t i = ((size_t)blk * 256 + threadIdx.x) * 4;
    float4 v = *(const float4*)(src + i);
    uint2 u;
    u.x = pack_h2(v.x, v.y);
    u.y = pack_h2(v.z, v.w);
    *(uint2*)(dst + i) = u;
}

// ---------------------------------------------------------------------------
// fp16 NT GEMM, 128x128 tile, K-chunk 64, 3-stage cp.async, m16n8k16 mma.
// PROJ=false: merged QKV (grid y 0..31) + KV (y 32..35) projection with
//             RMSNorm fused into the epilogue (fp32, pre-rounding).
// PROJ=true : output projection from g_ao, fp32 result + bias.
// ---------------------------------------------------------------------------
#define GSTR 72
#define GSTAGE (2 * 128 * GSTR)            // halves per stage
#define GEMM_SMEM (3 * GSTAGE * 2)         // 110592 bytes

template <bool PROJ>
__global__ __launch_bounds__(256, 2) void gemm_mma(const float* __restrict__ biasA,
                                                   const float* __restrict__ biasB,
                                                   const float* __restrict__ qn,
                                                   const float* __restrict__ kn,
                                                   float* __restrict__ outp)
{
    extern __shared__ __half smh[];
    const uint32_t sbase = smem_u32(smh);

    const int tid  = threadIdx.x;
    const int lane = tid & 31;
    const int wid  = tid >> 5;
    const int wm   = wid >> 2;
    const int wn   = wid & 3;
    const int gid  = lane >> 2;
    const int tig  = lane & 3;

    const int colBase = blockIdx.x * 128;
    int mode, rowBase;
    const __half *Aptr, *Wptr;
    const float* bias;
    if (PROJ) {
        mode = 2; rowBase = blockIdx.y * 128;
        Aptr = g_ao; Wptr = g_wp; bias = biasA;
    } else {
        const bool m1 = blockIdx.y >= 32;
        if (m1 && blockIdx.x >= 16) return;     // KV proj has only 16 col-blocks
        mode = m1 ? 1 : 0;
        rowBase = (m1 ? (blockIdx.y - 32) : blockIdx.y) * 128;
        Aptr = m1 ? g_yh : g_xh;
        Wptr = m1 ? g_wkv : g_wqkv;
        bias = m1 ? biasB : biasA;
    }

    const int u_row = tid >> 1;
    const int u_s4  = (tid & 1) * 4;

    auto issue_stage = [&](int stage, int k0) {
        const uint32_t aOff = sbase + (uint32_t)(stage * GSTAGE) * 2;
        const uint32_t bOff = aOff + 128 * GSTR * 2;
#pragma unroll
        for (int i = 0; i < 4; i++) {
            const int seg = u_s4 + i;
            const uint32_t d = (uint32_t)(u_row * GSTR + seg * 8) * 2;
            CP16(aOff + d, Aptr + (size_t)(rowBase + u_row) * CC + k0 + seg * 8);
            CP16(bOff + d, Wptr + (size_t)(colBase + u_row) * CC + k0 + seg * 8);
        }
        CP_COMMIT();
    };

    float c[4][4][4];
#pragma unroll
    for (int mt = 0; mt < 4; mt++)
#pragma unroll
        for (int nt = 0; nt < 4; nt++)
#pragma unroll
            for (int q = 0; q < 4; q++) c[mt][nt][q] = 0.f;

    issue_stage(0, 0);
    issue_stage(1, 64);

    const int lr8  = lane & 7;
    const int aRow = (lane >> 3) & 1;
    const int aCol = lane >> 4;

    for (int chunk = 0; chunk < 16; ++chunk) {
        CP_WAIT1();
        __syncthreads();

        if (chunk + 2 < 16) issue_stage((chunk + 2) % 3, (chunk + 2) * 64);
        else CP_COMMIT();

        const int st = chunk % 3;
        const uint32_t aB = sbase + (uint32_t)(st * GSTAGE) * 2;
        const uint32_t bB = aB + 128 * GSTR * 2;

#pragma unroll
        for (int kk = 0; kk < 4; kk++) {
            uint32_t a[4][4];
#pragma unroll
            for (int mt = 0; mt < 4; mt++)
                LDSM4(a[mt][0], a[mt][1], a[mt][2], a[mt][3],
                      aB + (uint32_t)((wm * 64 + mt * 16 + lr8 + aRow * 8) * GSTR
                                      + kk * 16 + aCol * 8) * 2);
#pragma unroll
            for (int p = 0; p < 2; p++) {
                uint32_t b0, b1, b2, b3;
                LDSM4(b0, b1, b2, b3,
                      bB + (uint32_t)((wn * 32 + p * 16 + lr8 + aCol * 8) * GSTR
                                      + kk * 16 + aRow * 8) * 2);
#pragma unroll
                for (int mt = 0; mt < 4; mt++) {
                    mma_h(c[mt][2 * p],     a[mt][0], a[mt][1], a[mt][2], a[mt][3], b0, b1);
                    mma_h(c[mt][2 * p + 1], a[mt][0], a[mt][1], a[mt][2], a[mt][3], b2, b3);
                }
            }
        }
    }

    // ---- epilogue: bias (fp32) ----
#pragma unroll
    for (int nt = 0; nt < 4; nt++) {
        const float2 bv = *(const float2*)&bias[colBase + wn * 32 + nt * 8 + tig * 2];
#pragma unroll
        for (int mt = 0; mt < 4; mt++) {
            c[mt][nt][0] += bv.x; c[mt][nt][1] += bv.y;
            c[mt][nt][2] += bv.x; c[mt][nt][3] += bv.y;
        }
    }

    // ---- fused RMSNorm (q/k segments only), fp32 before fp16 rounding ----
    if (!PROJ) {
        const int seg = colBase >> 10;               // uniform per block
        const bool donorm = (mode == 0) ? (seg <= 1) : (seg == 0);
        if (donorm) {
            const float* w = (mode == 0 && seg == 0) ? qn : kn;
            const float sc = (mode == 0 && seg == 0) ? QSCALE : 1.0f;

            float ssq[4][2];
#pragma unroll
            for (int mt = 0; mt < 4; mt++)
#pragma unroll
                for (int hf = 0; hf < 2; hf++) {
                    float s = 0.f;
#pragma unroll
                    for (int nt = 0; nt < 4; nt++) {
                        const float x0 = c[mt][nt][hf * 2 + 0];
                        const float x1 = c[mt][nt][hf * 2 + 1];
                        s += x0 * x0 + x1 * x1;
                    }
                    s += __shfl_xor_sync(0xffffffffu, s, 1);
                    s += __shfl_xor_sync(0xffffffffu, s, 2);
                    ssq[mt][hf] = s;                 // 32-col partial (this warp)
                }
            // cross-warp (wn ^ 1 shares the same 64-col head)
            float* red = (float*)smh;                // [wid][mt*2+hf][gid]
            __syncthreads();                         // mainloop smem reads done
            if (tig == 0) {
#pragma unroll
                for (int mt = 0; mt < 4; mt++)
#pragma unroll
                    for (int hf = 0; hf < 2; hf++)
                        red[(wid * 8 + mt * 2 + hf) * 8 + gid] = ssq[mt][hf];
            }
            __syncthreads();
            float2 wv[4];
#pragma unroll
            for (int nt = 0; nt < 4; nt++)
                wv[nt] = *(const float2*)&w[(wn & 1) * 32 + nt * 8 + tig * 2];
#pragma unroll
            for (int mt = 0; mt < 4; mt++)
#pragma unroll
                for (int hf = 0; hf < 2; hf++) {
                    const float tot = ssq[mt][hf] +
                        red[((wid ^ 1) * 8 + mt * 2 + hf) * 8 + gid];
                    const float inv = rsqrtf(tot * (1.0f / 64.0f) + 1e-6f) * sc;
#pragma unroll
                    for (int nt = 0; nt < 4; nt++) {
                        c[mt][nt][hf * 2 + 0] *= inv * wv[nt].x;
                        c[mt][nt][hf * 2 + 1] *= inv * wv[nt].y;
                    }
                }
        }
    }

    // ---- scatter ----
#pragma unroll
    for (int mt = 0; mt < 4; mt++)
#pragma unroll
        for (int nt = 0; nt < 4; nt++)
#pragma unroll
            for (int hf = 0; hf < 2; hf++) {
                const int row = rowBase + wm * 64 + mt * 16 + gid + hf * 8;
                const int col = colBase + wn * 32 + nt * 8 + tig * 2;
                const float vx = c[mt][nt][hf * 2 + 0];
                const float vy = c[mt][nt][hf * 2 + 1];
                if (PROJ) {
                    float2 v; v.x = vx; v.y = vy;
                    *(float2*)(outp + (size_t)row * CC + col) = v;
                } else {
                    __half* dst;
                    if (mode == 0) {
                        const int b_ = row >> 11, n = row & (NN - 1);
                        const int t3 = col >> 10, h = (col >> 6) & 15, d = col & 63;
                        const size_t bh = (size_t)b_ * HH + h;
                        if (t3 == 0)      dst = g_q + (bh * NN + n) * HD + d;
                        else if (t3 == 1) dst = g_k + (bh * SS + n) * HD + d;
                        else              dst = g_v + (bh * SS + n) * HD + d;
                    } else {
                        const int b_ = row >> 8, mm = row & (MM - 1);
                        const int t2 = col >> 10, h = (col >> 6) & 15, d = col & 63;
                        const size_t bh = (size_t)b_ * HH + h;
                        dst = (t2 == 0) ? g_k + (bh * SS + NN + mm) * HD + d
                                        : g_v + (bh * SS + NN + mm) * HD + d;
                    }
                    *(__half2*)dst = __floats2half2_rn(vx, vy);
                }
            }
}

// ---------------------------------------------------------------------------
// fp16 flash attention; Q and P in registers; fp32 ex2 softmax (shift folded
// into accumulator init); l via ones-column mma. S-chunks of 64 (36 iters).
// smem: 3 stages x (K[64][72] + V[64][72]) halves = 55296 B.
// ---------------------------------------------------------------------------
#define ASTR 72
#define KVSTG (2 * 64 * ASTR)              // halves per stage (K+V)
#define ATTN_SMEM (3 * KVSTG * 2)          // 55296 bytes

__global__ __launch_bounds__(256, 2) void attn_mma()
{
    extern __shared__ __half sh[];
    const uint32_t sbase = smem_u32(sh);

    const int tid  = threadIdx.x;
    const int lane = tid & 31;
    const int wid  = tid >> 5;
    const int gid  = lane >> 2;
    const int tig  = lane & 3;
    const int lr8  = lane & 7;
    const int aRow = (lane >> 3) & 1;
    const int aCol = lane >> 4;

    const int qb = blockIdx.x * 128;
    const int h  = blockIdx.y;
    const int b  = blockIdx.z;
    const size_t bh = (size_t)b * HH + h;

    const __half* qg = g_q + (bh * NN + qb) * HD;
    const __half* kg = g_k + bh * SS * HD;
    const __half* vg = g_v + bh * SS * HD;

    const int kv_row = tid >> 2;
    const int kv_sg  = tid & 3;
    auto issue_stage = [&](int stage, int sc) {
        const uint32_t kOff = sbase + (uint32_t)(stage * KVSTG) * 2;
        const uint32_t vOff = kOff + 64 * ASTR * 2;
#pragma unroll
        for (int i = 0; i < 2; i++) {
            const int seg = kv_sg * 2 + i;
            const uint32_t d = (uint32_t)(kv_row * ASTR + seg * 8) * 2;
            CP16(kOff + d, kg + (size_t)(sc + kv_row) * HD + seg * 8);
            CP16(vOff + d, vg + (size_t)(sc + kv_row) * HD + seg * 8);
        }
        CP_COMMIT();
    };

    issue_stage(0, 0);
    issue_stage(1, 64);

    // stage Q through the stage-2 region, pull into fragments
    const int wrow = wid * 16;
    uint32_t qf[4][4];
    {
        __half* qsm = sh + 2 * KVSTG;
#pragma unroll
        for (int i = 0; i < 4; i++) {
            const int u = tid + 256 * i;
            const int row = u >> 3, seg = u & 7;
            *(uint4*)&qsm[row * ASTR + seg * 8] =
                *(const uint4*)&qg[(size_t)row * HD + seg * 8];
        }
        __syncthreads();
        const uint32_t qB = sbase + (uint32_t)(2 * KVSTG) * 2;
#pragma unroll
        for (int kk = 0; kk < 4; kk++)
            LDSM4(qf[kk][0], qf[kk][1], qf[kk][2], qf[kk][3],
                  qB + (uint32_t)((wrow + lr8 + aRow * 8) * ASTR
                                  + kk * 16 + aCol * 8) * 2);
        __syncthreads();
    }

    float oacc[8][4];
#pragma unroll
    for (int nt = 0; nt < 8; nt++)
#pragma unroll
        for (int q = 0; q < 4; q++) oacc[nt][q] = 0.f;
    float lacc[4] = {0.f, 0.f, 0.f, 0.f};

    for (int c = 0; c < 36; ++c) {
        CP_WAIT1();
        __syncthreads();

        if (c + 2 < 36) issue_stage((c + 2) % 3, (c + 2) * 64);
        else CP_COMMIT();

        const int st = c % 3;
        const uint32_t ksB = sbase + (uint32_t)(st * KVSTG) * 2;
        const uint32_t vsB = ksB + 64 * ASTR * 2;

        // ---- S = Q @ K^T - CSH (shift folded into init) ----
        float s[8][4];
#pragma unroll
        for (int nt = 0; nt < 8; nt++)
#pragma unroll
            for (int q = 0; q < 4; q++) s[nt][q] = -CSH;

#pragma unroll
        for (int kk = 0; kk < 4; kk++) {
#pragma unroll
            for (int p = 0; p < 4; p++) {
                uint32_t b0, b1, b2, b3;
                LDSM4(b0, b1, b2, b3,
                      ksB + (uint32_t)((p * 16 + lr8 + aCol * 8) * ASTR
                                       + kk * 16 + aRow * 8) * 2);
                mma_h(s[2 * p],     qf[kk][0], qf[kk][1], qf[kk][2], qf[kk][3], b0, b1);
                mma_h(s[2 * p + 1], qf[kk][0], qf[kk][1], qf[kk][2], qf[kk][3], b2, b3);
            }
        }

        // ---- softmax: p = 2^S, fp32 ex2 then pack to fp16 ----
        uint32_t hlo[8], hhi[8];
#pragma unroll
        for (int nt = 0; nt < 8; nt++) {
            hlo[nt] = pack_h2(ex2f(s[nt][0]), ex2f(s[nt][1]));
            hhi[nt] = pack_h2(ex2f(s[nt][2]), ex2f(s[nt][3]));
        }

        // ---- l via ones-column mma; O += P @ V ----
#pragma unroll
        for (int kk = 0; kk < 4; kk++) {
            const uint32_t a0 = hlo[2 * kk],     a1 = hhi[2 * kk];
            const uint32_t a2 = hlo[2 * kk + 1], a3 = hhi[2 * kk + 1];
            mma_h(lacc, a0, a1, a2, a3, HONES, HONES);
#pragma unroll
            for (int p = 0; p < 4; p++) {
                uint32_t b0, b1, b2, b3;
                LDSM4T(b0, b1, b2, b3,
                       vsB + (uint32_t)((kk * 16 + lr8 + aRow * 8) * ASTR
                                        + p * 16 + aCol * 8) * 2);
                mma_h(oacc[2 * p],     a0, a1, a2, a3, b0, b1);
                mma_h(oacc[2 * p + 1], a0, a1, a2, a3, b2, b3);
            }
        }
    }

    // ---- epilogue: normalize, write fp16 ----
    const float inv0 = 1.0f / lacc[0];
    const float inv1 = 1.0f / lacc[2];
    const int n0 = qb + wrow + gid;
    const int n1 = n0 + 8;
#pragma unroll
    for (int nt = 0; nt < 8; nt++) {
        const int d = h * HD + nt * 8 + tig * 2;
        *(__half2*)&g_ao[((size_t)b * NN + n0) * CC + d] =
            __floats2half2_rn(oacc[nt][0] * inv0, oacc[nt][1] * inv0);
        *(__half2*)&g_ao[((size_t)b * NN + n1) * CC + d] =
            __floats2half2_rn(oacc[nt][2] * inv1, oacc[nt][3] * inv1);
    }
}

// ---------------------------------------------------------------------------
extern "C" void kernel_launch(void* const* d_in, const int* in_sizes, int n_in,
                              void* d_out, int out_size)
{
    const float* x      = (const float*)d_in[0];
    const float* y      = (const float*)d_in[1];
    const float* qkv_w  = (const float*)d_in[2];
    const float* qkv_b  = (const float*)d_in[3];
    const float* kv_w   = (const float*)d_in[4];
    const float* kv_b   = (const float*)d_in[5];
    const float* qn_w   = (const float*)d_in[6];
    const float* kn_w   = (const float*)d_in[7];
    const float* proj_w = (const float*)d_in[8];
    const float* proj_b = (const float*)d_in[9];
    float* out = (float*)d_out;

    (void)in_sizes; (void)n_in; (void)out_size;

    cudaFuncSetAttribute(gemm_mma<false>, cudaFuncAttributeMaxDynamicSharedMemorySize, GEMM_SMEM);
    cudaFuncSetAttribute(gemm_mma<true>,  cudaFuncAttributeMaxDynamicSharedMemorySize, GEMM_SMEM);
    cudaFuncSetAttribute(attn_mma, cudaFuncAttributeMaxDynamicSharedMemorySize, ATTN_SMEM);

    // 1) merged fp32->fp16 conversion pass
    cvt_all<<<CVT_BLOCKS, 256>>>(x, y, qkv_w, kv_w, proj_w);

    // 2) merged QKV + KV projections with fused RMSNorm epilogue
    gemm_mma<false><<<dim3(24, 36), 256, GEMM_SMEM>>>(qkv_b, kv_b, qn_w, kn_w, nullptr);

    // 3) attention
    attn_mma<<<dim3(NN / 128, HH, BB), 256, ATTN_SMEM>>>();

    // 4) output projection -> d_out
    gemm_mma<true><<<dim3(8, 32), 256, GEMM_SMEM>>>(proj_b, nullptr, nullptr, nullptr, out);
}